// round 1
// baseline (speedup 1.0000x reference)
#include <cuda_runtime.h>
#include <math.h>

// ---------------- problem constants ----------------
#define BB   16
#define NN   2048
#define DD   1024
#define HH   8
#define DHD  64
#define II   512           // H*DH
#define LQ   64
#define SSQ  2112          // N + L  (= 33 * 64)
#define NDEPTH 6
#define FFD  4096

// ---------------- scratch (device globals; no runtime alloc) ----------------
__device__ float g_xhat[(size_t)BB * NN * DD];       // 128 MB, layer-invariant LN core of x
__device__ float g_lat [BB * LQ * DD];
__device__ float g_lnl [BB * LQ * DD];
__device__ float g_lnf [BB * LQ * DD];
__device__ float g_q   [BB * LQ * II];
__device__ float g_att [BB * LQ * II];
__device__ float g_k   [(size_t)BB * HH * SSQ * DHD]; // (B,H,S,DH)
__device__ float g_v   [(size_t)BB * HH * SSQ * DHD];
__device__ float g_hf  [BB * LQ * FFD];
__device__ float g_wkvp[DD * 2 * II];                 // ln_m_w-folded Wkv for current layer
__device__ float g_biaskv[2 * II];                    // ln_m_b @ Wkv for current layer

// ---------------- LayerNorm over D=1024 (one block per row, 256 thr x 4 elems) ----
__global__ __launch_bounds__(256) void ln_kernel(const float* __restrict__ in,
                                                 float* __restrict__ out,
                                                 const float* __restrict__ w,
                                                 const float* __restrict__ b)
{
    int row = blockIdx.x;
    int tid = threadIdx.x;
    const float4 xv = *(const float4*)(in + (size_t)row * DD + tid * 4);
    float s  = xv.x + xv.y + xv.z + xv.w;
    float ss = xv.x * xv.x + xv.y * xv.y + xv.z * xv.z + xv.w * xv.w;
    #pragma unroll
    for (int o = 16; o; o >>= 1) {
        s  += __shfl_xor_sync(0xffffffffu, s,  o);
        ss += __shfl_xor_sync(0xffffffffu, ss, o);
    }
    __shared__ float red[16];
    int wid = tid >> 5;
    if ((tid & 31) == 0) { red[wid] = s; red[wid + 8] = ss; }
    __syncthreads();
    s = 0.f; ss = 0.f;
    #pragma unroll
    for (int i = 0; i < 8; i++) { s += red[i]; ss += red[i + 8]; }
    float mu   = s * (1.f / DD);
    float var  = ss * (1.f / DD) - mu * mu;
    float rstd = rsqrtf(var + 1e-5f);
    float4 o4;
    o4.x = (xv.x - mu) * rstd;
    o4.y = (xv.y - mu) * rstd;
    o4.z = (xv.z - mu) * rstd;
    o4.w = (xv.w - mu) * rstd;
    if (w) {
        const float4 wv = *(const float4*)(w + tid * 4);
        const float4 bv = *(const float4*)(b + tid * 4);
        o4.x = o4.x * wv.x + bv.x;
        o4.y = o4.y * wv.y + bv.y;
        o4.z = o4.z * wv.z + bv.z;
        o4.w = o4.w * wv.w + bv.w;
    }
    *(float4*)(out + (size_t)row * DD + tid * 4) = o4;
}

// ---------------- lat init: broadcast latents across batch ----------------
__global__ void init_lat_kernel(const float* __restrict__ latents, float* __restrict__ lat)
{
    int idx = blockIdx.x * 256 + threadIdx.x;       // total 16*64*1024 = 1M
    lat[idx] = latents[idx & (LQ * DD - 1)];
}

// ---------------- fold ln_m_w into Wkv (per layer) ----------------
__global__ void fold_wkv_kernel(const float* __restrict__ Wkv, const float* __restrict__ lw,
                                float* __restrict__ outW)
{
    int idx = blockIdx.x * 256 + threadIdx.x;       // D * 2I = 1M
    outW[idx] = lw[idx >> 10] * Wkv[idx];
}

// ---------------- biaskv[j] = sum_d ln_m_b[d] * Wkv[d][j]  (deterministic) ----
__global__ void bias_kv_kernel(const float* __restrict__ Wkv, const float* __restrict__ lnb,
                               float* __restrict__ bias)
{
    // 32 blocks; block handles 32 j columns; 8 d-chunks of 128 each
    int j  = blockIdx.x * 32 + (threadIdx.x & 31);
    int dc = threadIdx.x >> 5;
    float a = 0.f;
    int d0 = dc * 128;
    #pragma unroll 8
    for (int d = d0; d < d0 + 128; d++) a += lnb[d] * Wkv[(size_t)d * 1024 + j];
    __shared__ float red[8][32];
    red[dc][threadIdx.x & 31] = a;
    __syncthreads();
    if (dc == 0) {
        float s = 0.f;
        #pragma unroll
        for (int i = 0; i < 8; i++) s += red[i][threadIdx.x & 31];
        bias[j] = s;
    }
}

// ---------------- generic fp32 GEMM: C(MxN) = A(MxK) @ B(KxN), 128x128x16 tiles ----
enum { EPI_NONE = 0, EPI_ADD = 1, EPI_GELU = 2, EPI_KV = 3 };

__global__ __launch_bounds__(256, 2) void gemm_kernel(
    const float* __restrict__ A, const float* __restrict__ B, float* __restrict__ C,
    int M, int N, int K, int epi,
    const float* __restrict__ bias,
    float* __restrict__ Kout, float* __restrict__ Vout,
    int rowsPerB, int sBase)
{
    __shared__ float As[16][132];   // transposed A tile, padded
    __shared__ float Bs[16][128];

    int tid = threadIdx.x;
    int tx = tid & 15, ty = tid >> 4;
    int row0 = blockIdx.y << 7, col0 = blockIdx.x << 7;

    int ar = tid >> 2, ak = (tid & 3) << 2;     // A: rows ar, ar+64 at k-cols ak..ak+3
    int br = tid >> 5, bc = (tid & 31) << 2;    // B: rows br, br+8  at cols bc..bc+3

    const float* Aptr0 = A + (size_t)(row0 + ar) * K + ak;
    const float* Aptr1 = Aptr0 + (size_t)64 * K;
    const float* Bptr0 = B + (size_t)br * N + col0 + bc;
    const float* Bptr1 = Bptr0 + (size_t)8 * N;

    float acc[8][8];
    #pragma unroll
    for (int i = 0; i < 8; i++)
        #pragma unroll
        for (int j = 0; j < 8; j++) acc[i][j] = 0.f;

    for (int kt = 0; kt < K; kt += 16) {
        float4 a0 = *(const float4*)(Aptr0 + kt);
        float4 a1 = *(const float4*)(Aptr1 + kt);
        float4 b0 = *(const float4*)(Bptr0 + (size_t)kt * N);
        float4 b1 = *(const float4*)(Bptr1 + (size_t)kt * N);
        __syncthreads();
        As[ak + 0][ar] = a0.x; As[ak + 1][ar] = a0.y;
        As[ak + 2][ar] = a0.z; As[ak + 3][ar] = a0.w;
        As[ak + 0][ar + 64] = a1.x; As[ak + 1][ar + 64] = a1.y;
        As[ak + 2][ar + 64] = a1.z; As[ak + 3][ar + 64] = a1.w;
        *(float4*)&Bs[br][bc]     = b0;
        *(float4*)&Bs[br + 8][bc] = b1;
        __syncthreads();
        #pragma unroll
        for (int kk = 0; kk < 16; kk++) {
            float ra[8], rb[8];
            *(float4*)&ra[0] = *(const float4*)&As[kk][ty * 8];
            *(float4*)&ra[4] = *(const float4*)&As[kk][ty * 8 + 4];
            *(float4*)&rb[0] = *(const float4*)&Bs[kk][tx * 8];
            *(float4*)&rb[4] = *(const float4*)&Bs[kk][tx * 8 + 4];
            #pragma unroll
            for (int i = 0; i < 8; i++)
                #pragma unroll
                for (int j = 0; j < 8; j++)
                    acc[i][j] += ra[i] * rb[j];
        }
    }

    int rbase = row0 + ty * 8, cbase = col0 + tx * 8;
    if (epi == EPI_KV) {
        #pragma unroll
        for (int i = 0; i < 8; i++) {
            int r  = rbase + i;
            int bb = r / rowsPerB;
            int s  = sBase + (r - bb * rowsPerB);
            #pragma unroll
            for (int j = 0; j < 8; j++) {
                int c = cbase + j;
                float v = acc[i][j] + (bias ? bias[c] : 0.f);
                if (c < II) {
                    Kout[(((size_t)bb * HH + (c >> 6)) * SSQ + s) * DHD + (c & 63)] = v;
                } else {
                    int c2 = c - II;
                    Vout[(((size_t)bb * HH + (c2 >> 6)) * SSQ + s) * DHD + (c2 & 63)] = v;
                }
            }
        }
    } else {
        #pragma unroll
        for (int i = 0; i < 8; i++) {
            int r = rbase + i;
            #pragma unroll
            for (int j = 0; j < 8; j++) {
                int c = cbase + j;
                float v = acc[i][j];
                if (epi == EPI_ADD)       v += C[(size_t)r * N + c];
                else if (epi == EPI_GELU) v = 0.5f * v * (1.f + erff(v * 0.70710678118654752f));
                C[(size_t)r * N + c] = v;
            }
        }
    }
}

// ---------------- fused flash attention: one block per (b, h) ----------------
// q: (B,L,I) row-major;  k,v: (B,H,S,DH);  att out: (B,L,I)
#define ATTN_ST 68
#define ATTN_SMEM ((4 * 64 * ATTN_ST + 64) * 4)

__global__ __launch_bounds__(256) void attn_kernel(
    const float* __restrict__ q, const float* __restrict__ kg, const float* __restrict__ vg,
    const int* __restrict__ mask, float* __restrict__ att)
{
    extern __shared__ float sm[];
    float* qs  = sm;
    float* ks  = sm + 64 * ATTN_ST;
    float* vs  = sm + 2 * 64 * ATTN_ST;
    float* ps  = sm + 3 * 64 * ATTN_ST;
    float* msk = sm + 4 * 64 * ATTN_ST;

    int bh = blockIdx.x, b = bh >> 3, h = bh & 7;
    int tid = threadIdx.x;
    int qr = tid >> 2, c0 = (tid & 3) << 4;      // 4 threads per q-row, 16 dh cols each

    const float* qbase = q + (size_t)b * LQ * II + h * DHD;
    for (int idx = tid; idx < 64 * 16; idx += 256) {
        int r = idx >> 4, d4 = (idx & 15) << 2;
        *(float4*)&qs[r * ATTN_ST + d4] = *(const float4*)&qbase[(size_t)r * II + d4];
    }

    float acc[16];
    #pragma unroll
    for (int i = 0; i < 16; i++) acc[i] = 0.f;
    float m = -1e30f, l = 0.f;

    const float* kb = kg + ((size_t)b * HH + h) * SSQ * DHD;
    const float* vb = vg + ((size_t)b * HH + h) * SSQ * DHD;
    const int* mrow = mask + b * NN;

    for (int t = 0; t < SSQ / 64; t++) {
        int s0 = t * 64;
        __syncthreads();
        for (int idx = tid; idx < 64 * 16; idx += 256) {
            int r = idx >> 4, d4 = (idx & 15) << 2;
            *(float4*)&ks[r * ATTN_ST + d4] = *(const float4*)&kb[(size_t)(s0 + r) * DHD + d4];
            *(float4*)&vs[r * ATTN_ST + d4] = *(const float4*)&vb[(size_t)(s0 + r) * DHD + d4];
        }
        if (tid < 64) {
            int s = s0 + tid;
            msk[tid] = (s < NN && mrow[s] == 1) ? 1.f : 0.f;   // mask==1 -> exclude
        }
        __syncthreads();

        float sc[16];
        float tmax = -1e30f;
        const float* qrow = &qs[qr * ATTN_ST];
        #pragma unroll
        for (int j = 0; j < 16; j++) {
            const float* kr = &ks[(c0 + j) * ATTN_ST];
            float s = 0.f;
            #pragma unroll
            for (int d = 0; d < 64; d += 4) {
                float4 k4 = *(const float4*)&kr[d];
                float4 q4 = *(const float4*)&qrow[d];
                s += q4.x * k4.x + q4.y * k4.y + q4.z * k4.z + q4.w * k4.w;
            }
            s *= 0.125f;
            if (msk[c0 + j] != 0.f) s = -1e30f;
            sc[j] = s;
            tmax = fmaxf(tmax, s);
        }
        tmax = fmaxf(tmax, __shfl_xor_sync(0xffffffffu, tmax, 1));
        tmax = fmaxf(tmax, __shfl_xor_sync(0xffffffffu, tmax, 2));
        float mnew = fmaxf(m, tmax);
        float corr = __expf(m - mnew);
        float psum = 0.f;
        #pragma unroll
        for (int j = 0; j < 16; j++) {
            float p = __expf(sc[j] - mnew);
            ps[qr * ATTN_ST + c0 + j] = p;
            psum += p;
        }
        psum += __shfl_xor_sync(0xffffffffu, psum, 1);
        psum += __shfl_xor_sync(0xffffffffu, psum, 2);
        l = l * corr + psum;
        m = mnew;
        #pragma unroll
        for (int i = 0; i < 16; i++) acc[i] *= corr;
        __syncthreads();

        #pragma unroll 4
        for (int j = 0; j < 64; j++) {
            float p = ps[qr * ATTN_ST + j];
            float4 v0 = *(const float4*)&vs[j * ATTN_ST + c0];
            float4 v1 = *(const float4*)&vs[j * ATTN_ST + c0 + 4];
            float4 v2 = *(const float4*)&vs[j * ATTN_ST + c0 + 8];
            float4 v3 = *(const float4*)&vs[j * ATTN_ST + c0 + 12];
            acc[0]  += p * v0.x; acc[1]  += p * v0.y; acc[2]  += p * v0.z; acc[3]  += p * v0.w;
            acc[4]  += p * v1.x; acc[5]  += p * v1.y; acc[6]  += p * v1.z; acc[7]  += p * v1.w;
            acc[8]  += p * v2.x; acc[9]  += p * v2.y; acc[10] += p * v2.z; acc[11] += p * v2.w;
            acc[12] += p * v3.x; acc[13] += p * v3.y; acc[14] += p * v3.z; acc[15] += p * v3.w;
        }
    }

    float invl = 1.f / l;
    float* ob = att + ((size_t)(b * LQ) + qr) * II + h * DHD + c0;
    #pragma unroll
    for (int i = 0; i < 16; i++) ob[i] = acc[i] * invl;
}

// ---------------- host orchestration ----------------
extern "C" void kernel_launch(void* const* d_in, const int* in_sizes, int n_in,
                              void* d_out, int out_size)
{
    (void)in_sizes; (void)n_in; (void)out_size;
    const float* x        = (const float*)d_in[0];
    const int*   mask     = (const int*)  d_in[1];
    const float* latents  = (const float*)d_in[2];
    const float* ln_m_w   = (const float*)d_in[3];
    const float* ln_m_b   = (const float*)d_in[4];
    const float* ln_l_w   = (const float*)d_in[5];
    const float* ln_l_b   = (const float*)d_in[6];
    const float* Wq       = (const float*)d_in[7];
    const float* Wkv      = (const float*)d_in[8];
    const float* Wo       = (const float*)d_in[9];
    const float* ff_ln_w  = (const float*)d_in[10];
    const float* ff_ln_b  = (const float*)d_in[11];
    const float* W1       = (const float*)d_in[12];
    const float* W2       = (const float*)d_in[13];
    const float* norm_w   = (const float*)d_in[14];
    const float* norm_b   = (const float*)d_in[15];
    float* out = (float*)d_out;

    float *xhat, *lat, *lnl, *lnf, *qb, *attb, *kb, *vb, *hf, *wkvp, *biaskv;
    cudaGetSymbolAddress((void**)&xhat,   g_xhat);
    cudaGetSymbolAddress((void**)&lat,    g_lat);
    cudaGetSymbolAddress((void**)&lnl,    g_lnl);
    cudaGetSymbolAddress((void**)&lnf,    g_lnf);
    cudaGetSymbolAddress((void**)&qb,     g_q);
    cudaGetSymbolAddress((void**)&attb,   g_att);
    cudaGetSymbolAddress((void**)&kb,     g_k);
    cudaGetSymbolAddress((void**)&vb,     g_v);
    cudaGetSymbolAddress((void**)&hf,     g_hf);
    cudaGetSymbolAddress((void**)&wkvp,   g_wkvp);
    cudaGetSymbolAddress((void**)&biaskv, g_biaskv);

    cudaFuncSetAttribute(attn_kernel, cudaFuncAttributeMaxDynamicSharedMemorySize, ATTN_SMEM);

    // layer-invariant: xhat = (x - mu) * rstd ; lat = broadcast(latents)
    ln_kernel<<<BB * NN, 256>>>(x, xhat, nullptr, nullptr);
    init_lat_kernel<<<BB * LQ * DD / 256, 256>>>(latents, lat);

    for (int i = 0; i < NDEPTH; i++) {
        const float* Wkv_i = Wkv + (size_t)i * DD * 2 * II;
        const float* Wq_i  = Wq  + (size_t)i * DD * II;
        const float* Wo_i  = Wo  + (size_t)i * II * DD;
        const float* W1_i  = W1  + (size_t)i * DD * FFD;
        const float* W2_i  = W2  + (size_t)i * FFD * DD;

        // fold ln_m into Wkv  (xn @ Wkv == xhat @ Wkv' + biaskv)
        fold_wkv_kernel<<<DD * 2 * II / 256, 256>>>(Wkv_i, ln_m_w + i * DD, wkvp);
        bias_kv_kernel<<<32, 256>>>(Wkv_i, ln_m_b + i * DD, biaskv);

        // lnl = LN(lat)
        ln_kernel<<<BB * LQ, 256>>>(lat, lnl, ln_l_w + i * DD, ln_l_b + i * DD);

        // q = lnl @ Wq
        gemm_kernel<<<dim3(II / 128, BB * LQ / 128), 256>>>(
            lnl, Wq_i, qb, BB * LQ, II, DD, EPI_NONE, nullptr, nullptr, nullptr, 0, 0);

        // kv (x part): xhat @ Wkv' + biaskv -> scatter into K/V  (rows: b*N+s)
        gemm_kernel<<<dim3(2 * II / 128, BB * NN / 128), 256>>>(
            xhat, wkvp, nullptr, BB * NN, 2 * II, DD, EPI_KV, biaskv, kb, vb, NN, 0);

        // kv (latent part): lnl @ Wkv -> scatter into K/V rows s = N..S-1
        gemm_kernel<<<dim3(2 * II / 128, BB * LQ / 128), 256>>>(
            lnl, Wkv_i, nullptr, BB * LQ, 2 * II, DD, EPI_KV, nullptr, kb, vb, LQ, NN);

        // attention
        attn_kernel<<<BB * HH, 256, ATTN_SMEM>>>(qb, kb, vb, mask, attb);

        // lat += att @ Wo
        gemm_kernel<<<dim3(DD / 128, BB * LQ / 128), 256>>>(
            attb, Wo_i, lat, BB * LQ, DD, II, EPI_ADD, nullptr, nullptr, nullptr, 0, 0);

        // FF
        ln_kernel<<<BB * LQ, 256>>>(lat, lnf, ff_ln_w + i * DD, ff_ln_b + i * DD);
        gemm_kernel<<<dim3(FFD / 128, BB * LQ / 128), 256>>>(
            lnf, W1_i, hf, BB * LQ, FFD, DD, EPI_GELU, nullptr, nullptr, nullptr, 0, 0);
        gemm_kernel<<<dim3(DD / 128, BB * LQ / 128), 256>>>(
            hf, W2_i, lat, BB * LQ, DD, FFD, EPI_ADD, nullptr, nullptr, nullptr, 0, 0);
    }

    // final LN -> output (B,1,L,D) row-major
    ln_kernel<<<BB * LQ, 256>>>(lat, out, norm_w, norm_b);
}

// round 2
// speedup vs baseline: 1.5551x; 1.5551x over previous
#include <cuda_runtime.h>
#include <cuda_bf16.h>
#include <math.h>

// ---------------- problem constants ----------------
#define BB   16
#define NN   2048
#define DD   1024
#define HH   8
#define DHD  64
#define II   512           // H*DH
#define LQ   64
#define SSQ  2112          // N + L  (= 33 * 64)
#define NDEPTH 6
#define FFD  4096

// ---------------- scratch (device globals; no runtime alloc) ----------------
__device__ float g_xhat[(size_t)BB * NN * DD];       // 128 MB, layer-invariant LN core of x
__device__ float g_lat [BB * LQ * DD];
__device__ float g_lnl [BB * LQ * DD];
__device__ float g_lnf [BB * LQ * DD];
__device__ float g_q   [BB * LQ * II];
__device__ float g_att [BB * LQ * II];
__device__ float g_k   [(size_t)BB * HH * SSQ * DHD]; // (B,H,S,DH)
__device__ float g_v   [(size_t)BB * HH * SSQ * DHD];
__device__ float g_hf  [BB * LQ * FFD];
__device__ float g_wkvp[DD * 2 * II];                 // ln_m_w-folded Wkv for current layer
__device__ float g_biaskv[2 * II];                    // ln_m_b @ Wkv for current layer

// ---------------- LayerNorm over D=1024 ----------------
__global__ __launch_bounds__(256) void ln_kernel(const float* __restrict__ in,
                                                 float* __restrict__ out,
                                                 const float* __restrict__ w,
                                                 const float* __restrict__ b)
{
    int row = blockIdx.x;
    int tid = threadIdx.x;
    const float4 xv = *(const float4*)(in + (size_t)row * DD + tid * 4);
    float s  = xv.x + xv.y + xv.z + xv.w;
    float ss = xv.x * xv.x + xv.y * xv.y + xv.z * xv.z + xv.w * xv.w;
    #pragma unroll
    for (int o = 16; o; o >>= 1) {
        s  += __shfl_xor_sync(0xffffffffu, s,  o);
        ss += __shfl_xor_sync(0xffffffffu, ss, o);
    }
    __shared__ float red[16];
    int wid = tid >> 5;
    if ((tid & 31) == 0) { red[wid] = s; red[wid + 8] = ss; }
    __syncthreads();
    s = 0.f; ss = 0.f;
    #pragma unroll
    for (int i = 0; i < 8; i++) { s += red[i]; ss += red[i + 8]; }
    float mu   = s * (1.f / DD);
    float var  = ss * (1.f / DD) - mu * mu;
    float rstd = rsqrtf(var + 1e-5f);
    float4 o4;
    o4.x = (xv.x - mu) * rstd;
    o4.y = (xv.y - mu) * rstd;
    o4.z = (xv.z - mu) * rstd;
    o4.w = (xv.w - mu) * rstd;
    if (w) {
        const float4 wv = *(const float4*)(w + tid * 4);
        const float4 bv = *(const float4*)(b + tid * 4);
        o4.x = o4.x * wv.x + bv.x;
        o4.y = o4.y * wv.y + bv.y;
        o4.z = o4.z * wv.z + bv.z;
        o4.w = o4.w * wv.w + bv.w;
    }
    *(float4*)(out + (size_t)row * DD + tid * 4) = o4;
}

// ---------------- lat init ----------------
__global__ void init_lat_kernel(const float* __restrict__ latents, float* __restrict__ lat)
{
    int idx = blockIdx.x * 256 + threadIdx.x;
    lat[idx] = latents[idx & (LQ * DD - 1)];
}

// ---------------- fold ln_m_w into Wkv ----------------
__global__ void fold_wkv_kernel(const float* __restrict__ Wkv, const float* __restrict__ lw,
                                float* __restrict__ outW)
{
    int idx = blockIdx.x * 256 + threadIdx.x;
    outW[idx] = lw[idx >> 10] * Wkv[idx];
}

// ---------------- biaskv[j] = sum_d ln_m_b[d] * Wkv[d][j] ----------------
__global__ void bias_kv_kernel(const float* __restrict__ Wkv, const float* __restrict__ lnb,
                               float* __restrict__ bias)
{
    int j  = blockIdx.x * 32 + (threadIdx.x & 31);
    int dc = threadIdx.x >> 5;
    float a = 0.f;
    int d0 = dc * 128;
    #pragma unroll 8
    for (int d = d0; d < d0 + 128; d++) a += lnb[d] * Wkv[(size_t)d * 1024 + j];
    __shared__ float red[8][32];
    red[dc][threadIdx.x & 31] = a;
    __syncthreads();
    if (dc == 0) {
        float s = 0.f;
        #pragma unroll
        for (int i = 0; i < 8; i++) s += red[i][threadIdx.x & 31];
        bias[j] = s;
    }
}

// ================= bf16x3 split-precision tensor-core GEMM =================
// C(MxN) = A(MxK) @ B(KxN) in ~fp32 precision via 3 bf16 MMAs per tile.
enum { EPI_NONE = 0, EPI_ADD = 1, EPI_GELU = 2, EPI_KV = 3 };

#define GBM 128
#define GBN 128
#define GBK 32
#define AST 40    // As row stride (bf16 elems), conflict-free for ldmatrix
#define BST 136   // Bs row stride (bf16 elems)

__device__ __forceinline__ void mma16816(float* d, const unsigned* a, const unsigned* b)
{
    asm volatile(
        "mma.sync.aligned.m16n8k16.row.col.f32.bf16.bf16.f32 "
        "{%0,%1,%2,%3}, {%4,%5,%6,%7}, {%8,%9}, {%0,%1,%2,%3};\n"
        : "+f"(d[0]), "+f"(d[1]), "+f"(d[2]), "+f"(d[3])
        : "r"(a[0]), "r"(a[1]), "r"(a[2]), "r"(a[3]), "r"(b[0]), "r"(b[1]));
}

__device__ __forceinline__ void ldsm4(unsigned* r, unsigned addr)
{
    asm volatile("ldmatrix.sync.aligned.m8n8.x4.shared.b16 {%0,%1,%2,%3}, [%4];\n"
                 : "=r"(r[0]), "=r"(r[1]), "=r"(r[2]), "=r"(r[3]) : "r"(addr));
}

__device__ __forceinline__ void ldsm4t(unsigned* r, unsigned addr)
{
    asm volatile("ldmatrix.sync.aligned.m8n8.x4.trans.shared.b16 {%0,%1,%2,%3}, [%4];\n"
                 : "=r"(r[0]), "=r"(r[1]), "=r"(r[2]), "=r"(r[3]) : "r"(addr));
}

__device__ __forceinline__ unsigned pack2(float x, float y)
{
    __nv_bfloat16 hx = __float2bfloat16_rn(x);
    __nv_bfloat16 hy = __float2bfloat16_rn(y);
    return (unsigned)__bfloat16_as_ushort(hx) | ((unsigned)__bfloat16_as_ushort(hy) << 16);
}

__global__ __launch_bounds__(256) void gemm_kernel(
    const float* __restrict__ A, const float* __restrict__ B, float* __restrict__ C,
    int M, int N, int K, int epi,
    const float* __restrict__ bias,
    float* __restrict__ Kout, float* __restrict__ Vout,
    int rowsPerB, int sBase)
{
    __shared__ __align__(16) __nv_bfloat16 smbuf[2 * GBM * AST + 2 * GBK * BST];
    __nv_bfloat16* AsHi = smbuf;
    __nv_bfloat16* AsLo = AsHi + GBM * AST;
    __nv_bfloat16* BsHi = AsLo + GBM * AST;
    __nv_bfloat16* BsLo = BsHi + GBK * BST;

    unsigned smemBase = (unsigned)__cvta_generic_to_shared(smbuf);
    unsigned asHiB = smemBase;
    unsigned asLoB = asHiB + GBM * AST * 2;
    unsigned bsHiB = asLoB + GBM * AST * 2;
    unsigned bsLoB = bsHiB + GBK * BST * 2;

    int tid  = threadIdx.x;
    int lane = tid & 31;
    int warp = tid >> 5;
    int wm = warp & 1;          // 0..1 : 64-row strip
    int wn = warp >> 1;         // 0..3 : 32-col strip
    int row0 = blockIdx.y << 7;
    int col0 = blockIdx.x << 7;

    // ldmatrix lane->address mapping (same for A and B-trans)
    int lr = (lane & 7) + (((lane >> 3) & 1) << 3);
    int lc = (lane >> 4) << 3;

    // global load assignments (float4 granularity)
    int aRow = tid >> 3, aC4 = tid & 7;            // +256*i -> 4 rows apart... idx layout below
    int bK   = tid >> 5, bN4 = tid & 31;

    float acc[4][4][4];
    #pragma unroll
    for (int i = 0; i < 4; i++)
        #pragma unroll
        for (int j = 0; j < 4; j++)
            #pragma unroll
            for (int t = 0; t < 4; t++) acc[i][j][t] = 0.f;

    float4 pa[4], pb[4];

    // prologue loads (kt = 0)
    #pragma unroll
    for (int i = 0; i < 4; i++) {
        int idx = tid + 256 * i;                   // 0..1023
        int r = idx >> 3, c4 = idx & 7;
        pa[i] = *(const float4*)(A + (size_t)(row0 + r) * K + c4 * 4);
        int kk = idx >> 5, n4 = idx & 31;
        pb[i] = *(const float4*)(B + (size_t)kk * N + col0 + n4 * 4);
    }

    for (int kt = 0; kt < K; kt += GBK) {
        // convert + store to smem
        #pragma unroll
        for (int i = 0; i < 4; i++) {
            int idx = tid + 256 * i;
            int r = idx >> 3, c4 = idx & 7;
            float4 v = pa[i];
            float hx = __bfloat162float(__float2bfloat16_rn(v.x));
            float hy = __bfloat162float(__float2bfloat16_rn(v.y));
            float hz = __bfloat162float(__float2bfloat16_rn(v.z));
            float hw = __bfloat162float(__float2bfloat16_rn(v.w));
            uint2 hi = make_uint2(pack2(v.x, v.y), pack2(v.z, v.w));
            uint2 lo = make_uint2(pack2(v.x - hx, v.y - hy), pack2(v.z - hz, v.w - hw));
            *(uint2*)&AsHi[r * AST + c4 * 4] = hi;
            *(uint2*)&AsLo[r * AST + c4 * 4] = lo;

            int kk = idx >> 5, n4 = idx & 31;
            v = pb[i];
            hx = __bfloat162float(__float2bfloat16_rn(v.x));
            hy = __bfloat162float(__float2bfloat16_rn(v.y));
            hz = __bfloat162float(__float2bfloat16_rn(v.z));
            hw = __bfloat162float(__float2bfloat16_rn(v.w));
            hi = make_uint2(pack2(v.x, v.y), pack2(v.z, v.w));
            lo = make_uint2(pack2(v.x - hx, v.y - hy), pack2(v.z - hz, v.w - hw));
            *(uint2*)&BsHi[kk * BST + n4 * 4] = hi;
            *(uint2*)&BsLo[kk * BST + n4 * 4] = lo;
        }
        __syncthreads();

        // prefetch next tile
        if (kt + GBK < K) {
            #pragma unroll
            for (int i = 0; i < 4; i++) {
                int idx = tid + 256 * i;
                int r = idx >> 3, c4 = idx & 7;
                pa[i] = *(const float4*)(A + (size_t)(row0 + r) * K + kt + GBK + c4 * 4);
                int kk = idx >> 5, n4 = idx & 31;
                pb[i] = *(const float4*)(B + (size_t)(kt + GBK + kk) * N + col0 + n4 * 4);
            }
        }

        // compute: two k16 sub-steps
        #pragma unroll
        for (int k16 = 0; k16 < GBK; k16 += 16) {
            unsigned ah[4][4], al[4][4], bh[2][4], bl[2][4];
            #pragma unroll
            for (int mi = 0; mi < 4; mi++) {
                unsigned off = (unsigned)((wm * 64 + mi * 16 + lr) * AST + k16 + lc) * 2;
                ldsm4(ah[mi], asHiB + off);
                ldsm4(al[mi], asLoB + off);
            }
            #pragma unroll
            for (int ni = 0; ni < 2; ni++) {
                unsigned off = (unsigned)((k16 + lr) * BST + wn * 32 + ni * 16 + lc) * 2;
                ldsm4t(bh[ni], bsHiB + off);
                ldsm4t(bl[ni], bsLoB + off);
            }
            #pragma unroll
            for (int mi = 0; mi < 4; mi++) {
                #pragma unroll
                for (int nj = 0; nj < 4; nj++) {
                    int ni = nj >> 1, p = nj & 1;
                    mma16816(acc[mi][nj], ah[mi], &bh[ni][2 * p]);   // hi*hi
                    mma16816(acc[mi][nj], ah[mi], &bl[ni][2 * p]);   // hi*lo
                    mma16816(acc[mi][nj], al[mi], &bh[ni][2 * p]);   // lo*hi
                }
            }
        }
        __syncthreads();
    }

    // ---------------- epilogue ----------------
    int rbase = row0 + wm * 64 + (lane >> 2);
    int cbase = col0 + wn * 32 + (lane & 3) * 2;

    #pragma unroll
    for (int mi = 0; mi < 4; mi++) {
        #pragma unroll
        for (int nj = 0; nj < 4; nj++) {
            #pragma unroll
            for (int half = 0; half < 2; half++) {
                int r = rbase + mi * 16 + half * 8;
                int c = cbase + nj * 8;
                float v0 = acc[mi][nj][half * 2 + 0];
                float v1 = acc[mi][nj][half * 2 + 1];
                if (epi == EPI_KV) {
                    if (bias) { v0 += bias[c]; v1 += bias[c + 1]; }
                    int bb = r / rowsPerB;
                    int s  = sBase + (r - bb * rowsPerB);
                    float* dst;
                    if (c < II)
                        dst = Kout + (((size_t)bb * HH + (c >> 6)) * SSQ + s) * DHD + (c & 63);
                    else
                        dst = Vout + (((size_t)bb * HH + ((c - II) >> 6)) * SSQ + s) * DHD + ((c - II) & 63);
                    dst[0] = v0; dst[1] = v1;
                } else {
                    float* dst = C + (size_t)r * N + c;
                    if (epi == EPI_ADD) { v0 += dst[0]; v1 += dst[1]; }
                    else if (epi == EPI_GELU) {
                        v0 = 0.5f * v0 * (1.f + erff(v0 * 0.70710678118654752f));
                        v1 = 0.5f * v1 * (1.f + erff(v1 * 0.70710678118654752f));
                    }
                    dst[0] = v0; dst[1] = v1;
                }
            }
        }
    }
}

// ---------------- fused flash attention (unchanged) ----------------
#define ATTN_ST 68
#define ATTN_SMEM ((4 * 64 * ATTN_ST + 64) * 4)

__global__ __launch_bounds__(256) void attn_kernel(
    const float* __restrict__ q, const float* __restrict__ kg, const float* __restrict__ vg,
    const int* __restrict__ mask, float* __restrict__ att)
{
    extern __shared__ float sm[];
    float* qs  = sm;
    float* ks  = sm + 64 * ATTN_ST;
    float* vs  = sm + 2 * 64 * ATTN_ST;
    float* ps  = sm + 3 * 64 * ATTN_ST;
    float* msk = sm + 4 * 64 * ATTN_ST;

    int bh = blockIdx.x, b = bh >> 3, h = bh & 7;
    int tid = threadIdx.x;
    int qr = tid >> 2, c0 = (tid & 3) << 4;

    const float* qbase = q + (size_t)b * LQ * II + h * DHD;
    for (int idx = tid; idx < 64 * 16; idx += 256) {
        int r = idx >> 4, d4 = (idx & 15) << 2;
        *(float4*)&qs[r * ATTN_ST + d4] = *(const float4*)&qbase[(size_t)r * II + d4];
    }

    float acc[16];
    #pragma unroll
    for (int i = 0; i < 16; i++) acc[i] = 0.f;
    float m = -1e30f, l = 0.f;

    const float* kb = kg + ((size_t)b * HH + h) * SSQ * DHD;
    const float* vb = vg + ((size_t)b * HH + h) * SSQ * DHD;
    const int* mrow = mask + b * NN;

    for (int t = 0; t < SSQ / 64; t++) {
        int s0 = t * 64;
        __syncthreads();
        for (int idx = tid; idx < 64 * 16; idx += 256) {
            int r = idx >> 4, d4 = (idx & 15) << 2;
            *(float4*)&ks[r * ATTN_ST + d4] = *(const float4*)&kb[(size_t)(s0 + r) * DHD + d4];
            *(float4*)&vs[r * ATTN_ST + d4] = *(const float4*)&vb[(size_t)(s0 + r) * DHD + d4];
        }
        if (tid < 64) {
            int s = s0 + tid;
            msk[tid] = (s < NN && mrow[s] == 1) ? 1.f : 0.f;
        }
        __syncthreads();

        float sc[16];
        float tmax = -1e30f;
        const float* qrow = &qs[qr * ATTN_ST];
        #pragma unroll
        for (int j = 0; j < 16; j++) {
            const float* kr = &ks[(c0 + j) * ATTN_ST];
            float s = 0.f;
            #pragma unroll
            for (int d = 0; d < 64; d += 4) {
                float4 k4 = *(const float4*)&kr[d];
                float4 q4 = *(const float4*)&qrow[d];
                s += q4.x * k4.x + q4.y * k4.y + q4.z * k4.z + q4.w * k4.w;
            }
            s *= 0.125f;
            if (msk[c0 + j] != 0.f) s = -1e30f;
            sc[j] = s;
            tmax = fmaxf(tmax, s);
        }
        tmax = fmaxf(tmax, __shfl_xor_sync(0xffffffffu, tmax, 1));
        tmax = fmaxf(tmax, __shfl_xor_sync(0xffffffffu, tmax, 2));
        float mnew = fmaxf(m, tmax);
        float corr = __expf(m - mnew);
        float psum = 0.f;
        #pragma unroll
        for (int j = 0; j < 16; j++) {
            float p = __expf(sc[j] - mnew);
            ps[qr * ATTN_ST + c0 + j] = p;
            psum += p;
        }
        psum += __shfl_xor_sync(0xffffffffu, psum, 1);
        psum += __shfl_xor_sync(0xffffffffu, psum, 2);
        l = l * corr + psum;
        m = mnew;
        #pragma unroll
        for (int i = 0; i < 16; i++) acc[i] *= corr;
        __syncthreads();

        #pragma unroll 4
        for (int j = 0; j < 64; j++) {
            float p = ps[qr * ATTN_ST + j];
            float4 v0 = *(const float4*)&vs[j * ATTN_ST + c0];
            float4 v1 = *(const float4*)&vs[j * ATTN_ST + c0 + 4];
            float4 v2 = *(const float4*)&vs[j * ATTN_ST + c0 + 8];
            float4 v3 = *(const float4*)&vs[j * ATTN_ST + c0 + 12];
            acc[0]  += p * v0.x; acc[1]  += p * v0.y; acc[2]  += p * v0.z; acc[3]  += p * v0.w;
            acc[4]  += p * v1.x; acc[5]  += p * v1.y; acc[6]  += p * v1.z; acc[7]  += p * v1.w;
            acc[8]  += p * v2.x; acc[9]  += p * v2.y; acc[10] += p * v2.z; acc[11] += p * v2.w;
            acc[12] += p * v3.x; acc[13] += p * v3.y; acc[14] += p * v3.z; acc[15] += p * v3.w;
        }
    }

    float invl = 1.f / l;
    float* ob = att + ((size_t)(b * LQ) + qr) * II + h * DHD + c0;
    #pragma unroll
    for (int i = 0; i < 16; i++) ob[i] = acc[i] * invl;
}

// ---------------- host orchestration ----------------
extern "C" void kernel_launch(void* const* d_in, const int* in_sizes, int n_in,
                              void* d_out, int out_size)
{
    (void)in_sizes; (void)n_in; (void)out_size;
    const float* x        = (const float*)d_in[0];
    const int*   mask     = (const int*)  d_in[1];
    const float* latents  = (const float*)d_in[2];
    const float* ln_m_w   = (const float*)d_in[3];
    const float* ln_m_b   = (const float*)d_in[4];
    const float* ln_l_w   = (const float*)d_in[5];
    const float* ln_l_b   = (const float*)d_in[6];
    const float* Wq       = (const float*)d_in[7];
    const float* Wkv      = (const float*)d_in[8];
    const float* Wo       = (const float*)d_in[9];
    const float* ff_ln_w  = (const float*)d_in[10];
    const float* ff_ln_b  = (const float*)d_in[11];
    const float* W1       = (const float*)d_in[12];
    const float* W2       = (const float*)d_in[13];
    const float* norm_w   = (const float*)d_in[14];
    const float* norm_b   = (const float*)d_in[15];
    float* out = (float*)d_out;

    float *xhat, *lat, *lnl, *lnf, *qb, *attb, *kb, *vb, *hf, *wkvp, *biaskv;
    cudaGetSymbolAddress((void**)&xhat,   g_xhat);
    cudaGetSymbolAddress((void**)&lat,    g_lat);
    cudaGetSymbolAddress((void**)&lnl,    g_lnl);
    cudaGetSymbolAddress((void**)&lnf,    g_lnf);
    cudaGetSymbolAddress((void**)&qb,     g_q);
    cudaGetSymbolAddress((void**)&attb,   g_att);
    cudaGetSymbolAddress((void**)&kb,     g_k);
    cudaGetSymbolAddress((void**)&vb,     g_v);
    cudaGetSymbolAddress((void**)&hf,     g_hf);
    cudaGetSymbolAddress((void**)&wkvp,   g_wkvp);
    cudaGetSymbolAddress((void**)&biaskv, g_biaskv);

    cudaFuncSetAttribute(attn_kernel, cudaFuncAttributeMaxDynamicSharedMemorySize, ATTN_SMEM);

    ln_kernel<<<BB * NN, 256>>>(x, xhat, nullptr, nullptr);
    init_lat_kernel<<<BB * LQ * DD / 256, 256>>>(latents, lat);

    for (int i = 0; i < NDEPTH; i++) {
        const float* Wkv_i = Wkv + (size_t)i * DD * 2 * II;
        const float* Wq_i  = Wq  + (size_t)i * DD * II;
        const float* Wo_i  = Wo  + (size_t)i * II * DD;
        const float* W1_i  = W1  + (size_t)i * DD * FFD;
        const float* W2_i  = W2  + (size_t)i * FFD * DD;

        fold_wkv_kernel<<<DD * 2 * II / 256, 256>>>(Wkv_i, ln_m_w + i * DD, wkvp);
        bias_kv_kernel<<<32, 256>>>(Wkv_i, ln_m_b + i * DD, biaskv);

        ln_kernel<<<BB * LQ, 256>>>(lat, lnl, ln_l_w + i * DD, ln_l_b + i * DD);

        // q = lnl @ Wq
        gemm_kernel<<<dim3(II / GBN, BB * LQ / GBM), 256>>>(
            lnl, Wq_i, qb, BB * LQ, II, DD, EPI_NONE, nullptr, nullptr, nullptr, 0, 0);

        // kv (x part)
        gemm_kernel<<<dim3(2 * II / GBN, BB * NN / GBM), 256>>>(
            xhat, wkvp, nullptr, BB * NN, 2 * II, DD, EPI_KV, biaskv, kb, vb, NN, 0);

        // kv (latent part)
        gemm_kernel<<<dim3(2 * II / GBN, BB * LQ / GBM), 256>>>(
            lnl, Wkv_i, nullptr, BB * LQ, 2 * II, DD, EPI_KV, nullptr, kb, vb, LQ, NN);

        // attention
        attn_kernel<<<BB * HH, 256, ATTN_SMEM>>>(qb, kb, vb, mask, attb);

        // lat += att @ Wo
        gemm_kernel<<<dim3(DD / GBN, BB * LQ / GBM), 256>>>(
            attb, Wo_i, lat, BB * LQ, DD, II, EPI_ADD, nullptr, nullptr, nullptr, 0, 0);

        // FF
        ln_kernel<<<BB * LQ, 256>>>(lat, lnf, ff_ln_w + i * DD, ff_ln_b + i * DD);
        gemm_kernel<<<dim3(FFD / GBN, BB * LQ / GBM), 256>>>(
            lnf, W1_i, hf, BB * LQ, FFD, DD, EPI_GELU, nullptr, nullptr, nullptr, 0, 0);
        gemm_kernel<<<dim3(DD / GBN, BB * LQ / GBM), 256>>>(
            hf, W2_i, lat, BB * LQ, DD, FFD, EPI_ADD, nullptr, nullptr, nullptr, 0, 0);
    }

    ln_kernel<<<BB * LQ, 256>>>(lat, out, norm_w, norm_b);
}

// round 3
// speedup vs baseline: 2.3108x; 1.4860x over previous
#include <cuda_runtime.h>
#include <cuda_bf16.h>
#include <math.h>

// ---------------- problem constants ----------------
#define BB   16
#define NN   2048
#define DD   1024
#define HH   8
#define DHD  64
#define II   512           // H*DH
#define LQ   64
#define SSQ  2112          // N + L
#define NDEPTH 6
#define FFD  4096

typedef __nv_bfloat16 bf16;

// ---------------- scratch ----------------
__device__ bf16 g_xh[(size_t)BB * NN * DD];
__device__ bf16 g_xl[(size_t)BB * NN * DD];
__device__ bf16 g_lnlh[BB * LQ * DD],  g_lnll[BB * LQ * DD];
__device__ bf16 g_lnfh[BB * LQ * DD],  g_lnfl[BB * LQ * DD];
__device__ bf16 g_atth[BB * LQ * II],  g_attl[BB * LQ * II];
__device__ bf16 g_hfh [BB * LQ * FFD], g_hfl [BB * LQ * FFD];
__device__ bf16 g_wqh [DD * II],       g_wql [DD * II];
__device__ bf16 g_wkvh[DD * 2 * II],   g_wkvl[DD * 2 * II];
__device__ bf16 g_wkvph[DD * 2 * II],  g_wkvpl[DD * 2 * II];
__device__ bf16 g_woh [II * DD],       g_wol [II * DD];
__device__ bf16 g_w1h [DD * FFD],      g_w1l [DD * FFD];
__device__ bf16 g_w2h [FFD * DD],      g_w2l [FFD * DD];
__device__ float g_lat[BB * LQ * DD];
__device__ float g_q  [BB * LQ * II];
__device__ float g_k  [(size_t)BB * HH * SSQ * DHD];
__device__ float g_v  [(size_t)BB * HH * SSQ * DHD];
__device__ float g_biaskv[2 * II];

// ---------------- helpers ----------------
__device__ __forceinline__ unsigned pack2(float x, float y)
{
    bf16 hx = __float2bfloat16_rn(x);
    bf16 hy = __float2bfloat16_rn(y);
    return (unsigned)__bfloat16_as_ushort(hx) | ((unsigned)__bfloat16_as_ushort(hy) << 16);
}
__device__ __forceinline__ void split4(float4 v, uint2& hi, uint2& lo)
{
    float hx = __bfloat162float(__float2bfloat16_rn(v.x));
    float hy = __bfloat162float(__float2bfloat16_rn(v.y));
    float hz = __bfloat162float(__float2bfloat16_rn(v.z));
    float hw = __bfloat162float(__float2bfloat16_rn(v.w));
    hi = make_uint2(pack2(v.x, v.y), pack2(v.z, v.w));
    lo = make_uint2(pack2(v.x - hx, v.y - hy), pack2(v.z - hz, v.w - hw));
}

// ---------------- LayerNorm (fp32 out, final layer) ----------------
__global__ __launch_bounds__(256) void ln_kernel(const float* __restrict__ in,
                                                 float* __restrict__ out,
                                                 const float* __restrict__ w,
                                                 const float* __restrict__ b)
{
    int row = blockIdx.x;
    int tid = threadIdx.x;
    const float4 xv = *(const float4*)(in + (size_t)row * DD + tid * 4);
    float s  = xv.x + xv.y + xv.z + xv.w;
    float ss = xv.x * xv.x + xv.y * xv.y + xv.z * xv.z + xv.w * xv.w;
    #pragma unroll
    for (int o = 16; o; o >>= 1) {
        s  += __shfl_xor_sync(0xffffffffu, s,  o);
        ss += __shfl_xor_sync(0xffffffffu, ss, o);
    }
    __shared__ float red[16];
    int wid = tid >> 5;
    if ((tid & 31) == 0) { red[wid] = s; red[wid + 8] = ss; }
    __syncthreads();
    s = 0.f; ss = 0.f;
    #pragma unroll
    for (int i = 0; i < 8; i++) { s += red[i]; ss += red[i + 8]; }
    float mu   = s * (1.f / DD);
    float var  = ss * (1.f / DD) - mu * mu;
    float rstd = rsqrtf(var + 1e-5f);
    float4 o4;
    o4.x = (xv.x - mu) * rstd; o4.y = (xv.y - mu) * rstd;
    o4.z = (xv.z - mu) * rstd; o4.w = (xv.w - mu) * rstd;
    const float4 wv = *(const float4*)(w + tid * 4);
    const float4 bv = *(const float4*)(b + tid * 4);
    o4.x = o4.x * wv.x + bv.x; o4.y = o4.y * wv.y + bv.y;
    o4.z = o4.z * wv.z + bv.z; o4.w = o4.w * wv.w + bv.w;
    *(float4*)(out + (size_t)row * DD + tid * 4) = o4;
}

// ---------------- LayerNorm -> split bf16 hi/lo ----------------
__global__ __launch_bounds__(256) void ln_split_kernel(const float* __restrict__ in,
                                                       bf16* __restrict__ hi,
                                                       bf16* __restrict__ lo,
                                                       const float* __restrict__ w,
                                                       const float* __restrict__ b)
{
    int row = blockIdx.x;
    int tid = threadIdx.x;
    const float4 xv = *(const float4*)(in + (size_t)row * DD + tid * 4);
    float s  = xv.x + xv.y + xv.z + xv.w;
    float ss = xv.x * xv.x + xv.y * xv.y + xv.z * xv.z + xv.w * xv.w;
    #pragma unroll
    for (int o = 16; o; o >>= 1) {
        s  += __shfl_xor_sync(0xffffffffu, s,  o);
        ss += __shfl_xor_sync(0xffffffffu, ss, o);
    }
    __shared__ float red[16];
    int wid = tid >> 5;
    if ((tid & 31) == 0) { red[wid] = s; red[wid + 8] = ss; }
    __syncthreads();
    s = 0.f; ss = 0.f;
    #pragma unroll
    for (int i = 0; i < 8; i++) { s += red[i]; ss += red[i + 8]; }
    float mu   = s * (1.f / DD);
    float var  = ss * (1.f / DD) - mu * mu;
    float rstd = rsqrtf(var + 1e-5f);
    float4 o4;
    o4.x = (xv.x - mu) * rstd; o4.y = (xv.y - mu) * rstd;
    o4.z = (xv.z - mu) * rstd; o4.w = (xv.w - mu) * rstd;
    if (w) {
        const float4 wv = *(const float4*)(w + tid * 4);
        const float4 bv = *(const float4*)(b + tid * 4);
        o4.x = o4.x * wv.x + bv.x; o4.y = o4.y * wv.y + bv.y;
        o4.z = o4.z * wv.z + bv.z; o4.w = o4.w * wv.w + bv.w;
    }
    uint2 h, l;
    split4(o4, h, l);
    *(uint2*)(hi + (size_t)row * DD + tid * 4) = h;
    *(uint2*)(lo + (size_t)row * DD + tid * 4) = l;
}

// ---------------- generic split (weights), optional per-row(1024) scale ------
__global__ __launch_bounds__(256) void split_kernel(const float* __restrict__ in,
                                                    const float* __restrict__ rowscale,
                                                    bf16* __restrict__ hi,
                                                    bf16* __restrict__ lo)
{
    int idx = (blockIdx.x * 256 + threadIdx.x) * 4;
    float4 v = *(const float4*)(in + idx);
    if (rowscale) {
        float sc = rowscale[idx >> 10];
        v.x *= sc; v.y *= sc; v.z *= sc; v.w *= sc;
    }
    uint2 h, l;
    split4(v, h, l);
    *(uint2*)(hi + idx) = h;
    *(uint2*)(lo + idx) = l;
}

// ---------------- lat init ----------------
__global__ void init_lat_kernel(const float* __restrict__ latents, float* __restrict__ lat)
{
    int idx = blockIdx.x * 256 + threadIdx.x;
    lat[idx] = latents[idx & (LQ * DD - 1)];
}

// ---------------- biaskv[j] = sum_d ln_m_b[d] * Wkv[d][j] ----------------
__global__ void bias_kv_kernel(const float* __restrict__ Wkv, const float* __restrict__ lnb,
                               float* __restrict__ bias)
{
    int j  = blockIdx.x * 32 + (threadIdx.x & 31);
    int dc = threadIdx.x >> 5;
    float a = 0.f;
    int d0 = dc * 128;
    #pragma unroll 8
    for (int d = d0; d < d0 + 128; d++) a += lnb[d] * Wkv[(size_t)d * 1024 + j];
    __shared__ float red[8][32];
    red[dc][threadIdx.x & 31] = a;
    __syncthreads();
    if (dc == 0) {
        float s = 0.f;
        #pragma unroll
        for (int i = 0; i < 8; i++) s += red[i][threadIdx.x & 31];
        bias[j] = s;
    }
}

// ================= bf16x3 split-precision tensor-core GEMM =================
enum { EPI_NONE = 0, EPI_ADD = 1, EPI_GELU = 2, EPI_KV = 3 };

#define GBK 32
#define AST 40
#define BST 136

__device__ __forceinline__ void mma16816(float* d, const unsigned* a, const unsigned* b)
{
    asm volatile(
        "mma.sync.aligned.m16n8k16.row.col.f32.bf16.bf16.f32 "
        "{%0,%1,%2,%3}, {%4,%5,%6,%7}, {%8,%9}, {%0,%1,%2,%3};\n"
        : "+f"(d[0]), "+f"(d[1]), "+f"(d[2]), "+f"(d[3])
        : "r"(a[0]), "r"(a[1]), "r"(a[2]), "r"(a[3]), "r"(b[0]), "r"(b[1]));
}
__device__ __forceinline__ void ldsm4(unsigned* r, unsigned addr)
{
    asm volatile("ldmatrix.sync.aligned.m8n8.x4.shared.b16 {%0,%1,%2,%3}, [%4];\n"
                 : "=r"(r[0]), "=r"(r[1]), "=r"(r[2]), "=r"(r[3]) : "r"(addr));
}
__device__ __forceinline__ void ldsm4t(unsigned* r, unsigned addr)
{
    asm volatile("ldmatrix.sync.aligned.m8n8.x4.trans.shared.b16 {%0,%1,%2,%3}, [%4];\n"
                 : "=r"(r[0]), "=r"(r[1]), "=r"(r[2]), "=r"(r[3]) : "r"(addr));
}
__device__ __forceinline__ void cpasync16(unsigned s, const void* g)
{
    asm volatile("cp.async.cg.shared.global [%0], [%1], 16;\n" :: "r"(s), "l"(g));
}
#define CP_COMMIT() asm volatile("cp.async.commit_group;\n")
#define CP_WAIT1()  asm volatile("cp.async.wait_group 1;\n")

template<int TM>
__global__ __launch_bounds__(256) void gemm_bf16(
    const bf16* __restrict__ Ahi, const bf16* __restrict__ Alo,
    const bf16* __restrict__ Bhi, const bf16* __restrict__ Blo,
    float* __restrict__ C, int M, int N, int K, int epi,
    const float* __restrict__ bias,
    float* __restrict__ Kout, float* __restrict__ Vout, int rowsPerB, int sBase,
    bf16* __restrict__ OutHi, bf16* __restrict__ OutLo)
{
    constexpr int WM16   = TM / 32;
    constexpr int A_EL   = TM * AST;
    constexpr int B_EL   = GBK * BST;
    constexpr int STAGE  = 2 * A_EL + 2 * B_EL;      // elements per stage
    extern __shared__ __align__(16) bf16 smg[];
    unsigned base = (unsigned)__cvta_generic_to_shared(smg);

    int tid  = threadIdx.x;
    int lane = tid & 31;
    int warp = tid >> 5;
    int wm = warp & 1, wn = warp >> 1;
    int row0 = blockIdx.y * TM;
    int col0 = blockIdx.x << 7;
    int lr = (lane & 7) + (((lane >> 3) & 1) << 3);
    int lc = (lane >> 4) << 3;

    float acc[WM16][4][4];
    #pragma unroll
    for (int i = 0; i < WM16; i++)
        #pragma unroll
        for (int j = 0; j < 4; j++)
            #pragma unroll
            for (int t = 0; t < 4; t++) acc[i][j][t] = 0.f;

    auto load_stage = [&](int kt, int buf) {
        unsigned sb = base + (unsigned)buf * STAGE * 2;
        constexpr int ACH = (TM * 4) / 256;
        #pragma unroll
        for (int p = 0; p < 2; p++) {
            const bf16* Ap = p ? Alo : Ahi;
            unsigned so = sb + (unsigned)p * A_EL * 2;
            #pragma unroll
            for (int i = 0; i < ACH; i++) {
                int chunk = tid + i * 256;
                int r = chunk >> 2, c16 = chunk & 3;
                cpasync16(so + (unsigned)(r * AST + c16 * 8) * 2,
                          Ap + (size_t)(row0 + r) * K + kt + c16 * 8);
            }
        }
        #pragma unroll
        for (int p = 0; p < 2; p++) {
            const bf16* Bp = p ? Blo : Bhi;
            unsigned so = sb + (unsigned)(2 * A_EL + p * B_EL) * 2;
            #pragma unroll
            for (int i = 0; i < 2; i++) {
                int chunk = tid + i * 256;
                int r = chunk >> 4, cc = (chunk & 15) * 8;
                cpasync16(so + (unsigned)(r * BST + cc) * 2,
                          Bp + (size_t)(kt + r) * N + col0 + cc);
            }
        }
    };

    int NK = K / GBK;
    load_stage(0, 0);   CP_COMMIT();
    load_stage(GBK, 1); CP_COMMIT();

    for (int it = 0; it < NK; it++) {
        CP_WAIT1();
        __syncthreads();
        unsigned sb  = base + (unsigned)(it & 1) * STAGE * 2;
        unsigned aHi = sb;
        unsigned aLo = sb + A_EL * 2;
        unsigned bHi = sb + 2 * A_EL * 2;
        unsigned bLo = bHi + B_EL * 2;

        #pragma unroll
        for (int k16 = 0; k16 < GBK; k16 += 16) {
            unsigned ah[WM16][4], al[WM16][4], bh[2][4], bl[2][4];
            #pragma unroll
            for (int mi = 0; mi < WM16; mi++) {
                unsigned off = (unsigned)((wm * (TM / 2) + mi * 16 + lr) * AST + k16 + lc) * 2;
                ldsm4(ah[mi], aHi + off);
                ldsm4(al[mi], aLo + off);
            }
            #pragma unroll
            for (int ni = 0; ni < 2; ni++) {
                unsigned off = (unsigned)((k16 + lr) * BST + wn * 32 + ni * 16 + lc) * 2;
                ldsm4t(bh[ni], bHi + off);
                ldsm4t(bl[ni], bLo + off);
            }
            #pragma unroll
            for (int mi = 0; mi < WM16; mi++) {
                #pragma unroll
                for (int nj = 0; nj < 4; nj++) {
                    int ni = nj >> 1, p = nj & 1;
                    mma16816(acc[mi][nj], ah[mi], &bh[ni][2 * p]);
                    mma16816(acc[mi][nj], ah[mi], &bl[ni][2 * p]);
                    mma16816(acc[mi][nj], al[mi], &bh[ni][2 * p]);
                }
            }
        }
        __syncthreads();
        if (it + 2 < NK) load_stage((it + 2) * GBK, it & 1);
        CP_COMMIT();
    }

    // ---------------- epilogue ----------------
    int rbase = row0 + wm * (TM / 2) + (lane >> 2);
    int cbase = col0 + wn * 32 + (lane & 3) * 2;
    #pragma unroll
    for (int mi = 0; mi < WM16; mi++) {
        #pragma unroll
        for (int nj = 0; nj < 4; nj++) {
            #pragma unroll
            for (int half = 0; half < 2; half++) {
                int r = rbase + mi * 16 + half * 8;
                int c = cbase + nj * 8;
                float v0 = acc[mi][nj][half * 2 + 0];
                float v1 = acc[mi][nj][half * 2 + 1];
                if (epi == EPI_KV) {
                    if (bias) { v0 += bias[c]; v1 += bias[c + 1]; }
                    int bb = r / rowsPerB;
                    int s  = sBase + (r - bb * rowsPerB);
                    float* dst;
                    if (c < II)
                        dst = Kout + (((size_t)bb * HH + (c >> 6)) * SSQ + s) * DHD + (c & 63);
                    else
                        dst = Vout + (((size_t)bb * HH + ((c - II) >> 6)) * SSQ + s) * DHD + ((c - II) & 63);
                    dst[0] = v0; dst[1] = v1;
                } else if (epi == EPI_GELU) {
                    float h0 = 0.5f * v0 * (1.f + erff(v0 * 0.70710678118654752f));
                    float h1 = 0.5f * v1 * (1.f + erff(v1 * 0.70710678118654752f));
                    float t0 = __bfloat162float(__float2bfloat16_rn(h0));
                    float t1 = __bfloat162float(__float2bfloat16_rn(h1));
                    *(unsigned*)(OutHi + (size_t)r * N + c) = pack2(h0, h1);
                    *(unsigned*)(OutLo + (size_t)r * N + c) = pack2(h0 - t0, h1 - t1);
                } else {
                    float* dst = C + (size_t)r * N + c;
                    if (epi == EPI_ADD) { v0 += dst[0]; v1 += dst[1]; }
                    dst[0] = v0; dst[1] = v1;
                }
            }
        }
    }
}

// ---------------- fused flash attention v2 ----------------
// 2 CTAs per (b,h): each handles 32 q rows, all S. K stored d-major in smem.
#define AT2  68
#define ATTN_SMEM (((size_t)(32 + 64 + 64 + 32) * AT2 + 64) * 4)

__global__ __launch_bounds__(256) void attn_kernel(
    const float* __restrict__ q, const float* __restrict__ kg, const float* __restrict__ vg,
    const int* __restrict__ mask, bf16* __restrict__ attHi, bf16* __restrict__ attLo)
{
    extern __shared__ float sm[];
    float* qs  = sm;                              // [32][AT2] : q rows, d cols
    float* kT  = sm + 32 * AT2;                   // [64][AT2] : kT[d][s]
    float* vs  = sm + (32 + 64) * AT2;            // [64][AT2] : v rows s, d cols
    float* ps  = sm + (32 + 128) * AT2;           // [32][AT2]
    float* msk = sm + (32 + 160) * AT2;           // [64]

    int blk = blockIdx.x;
    int bh = blk >> 1, half = blk & 1;
    int b = bh >> 3, h = bh & 7;
    int tid = threadIdx.x;
    int qr = tid >> 3;                 // 0..31
    int j0 = (tid & 7) * 8;            // this thread's 8 score cols / 8 dh cols

    const float* qbase = q + ((size_t)(b * LQ) + half * 32) * II + h * DHD;
    for (int idx = tid; idx < 32 * 16; idx += 256) {
        int r = idx >> 4, d4 = (idx & 15) << 2;
        *(float4*)&qs[r * AT2 + d4] = *(const float4*)&qbase[(size_t)r * II + d4];
    }

    float acc[8];
    #pragma unroll
    for (int i = 0; i < 8; i++) acc[i] = 0.f;
    float m = -1e30f, l = 0.f;

    const float* kb = kg + ((size_t)b * HH + h) * SSQ * DHD;
    const float* vb = vg + ((size_t)b * HH + h) * SSQ * DHD;
    const int* mrow = mask + b * NN;

    for (int t = 0; t < SSQ / 64; t++) {
        int s0 = t * 64;
        __syncthreads();
        for (int idx = tid; idx < 64 * 16; idx += 256) {
            int r = idx >> 4, d4 = (idx & 15) << 2;
            float4 k4 = *(const float4*)&kb[(size_t)(s0 + r) * DHD + d4];
            kT[(d4 + 0) * AT2 + r] = k4.x;
            kT[(d4 + 1) * AT2 + r] = k4.y;
            kT[(d4 + 2) * AT2 + r] = k4.z;
            kT[(d4 + 3) * AT2 + r] = k4.w;
            *(float4*)&vs[r * AT2 + d4] = *(const float4*)&vb[(size_t)(s0 + r) * DHD + d4];
        }
        if (tid < 64) {
            int s = s0 + tid;
            msk[tid] = (s < NN && mrow[s] == 1) ? 1.f : 0.f;
        }
        __syncthreads();

        float sc[8];
        #pragma unroll
        for (int j = 0; j < 8; j++) sc[j] = 0.f;
        const float* qrow = &qs[qr * AT2];
        #pragma unroll 8
        for (int d = 0; d < 64; d++) {
            float qv = qrow[d];
            float4 kA = *(const float4*)&kT[d * AT2 + j0];
            float4 kB = *(const float4*)&kT[d * AT2 + j0 + 4];
            sc[0] += qv * kA.x; sc[1] += qv * kA.y; sc[2] += qv * kA.z; sc[3] += qv * kA.w;
            sc[4] += qv * kB.x; sc[5] += qv * kB.y; sc[6] += qv * kB.z; sc[7] += qv * kB.w;
        }
        float tmax = -1e30f;
        #pragma unroll
        for (int j = 0; j < 8; j++) {
            float s = sc[j] * 0.125f;
            if (msk[j0 + j] != 0.f) s = -1e30f;
            sc[j] = s;
            tmax = fmaxf(tmax, s);
        }
        tmax = fmaxf(tmax, __shfl_xor_sync(0xffffffffu, tmax, 1));
        tmax = fmaxf(tmax, __shfl_xor_sync(0xffffffffu, tmax, 2));
        tmax = fmaxf(tmax, __shfl_xor_sync(0xffffffffu, tmax, 4));
        float mnew = fmaxf(m, tmax);
        float corr = __expf(m - mnew);
        float psum = 0.f;
        #pragma unroll
        for (int j = 0; j < 8; j++) {
            float p = __expf(sc[j] - mnew);
            ps[qr * AT2 + j0 + j] = p;
            psum += p;
        }
        psum += __shfl_xor_sync(0xffffffffu, psum, 1);
        psum += __shfl_xor_sync(0xffffffffu, psum, 2);
        psum += __shfl_xor_sync(0xffffffffu, psum, 4);
        l = l * corr + psum;
        m = mnew;
        #pragma unroll
        for (int i = 0; i < 8; i++) acc[i] *= corr;
        __syncwarp();

        #pragma unroll 4
        for (int j = 0; j < 64; j++) {
            float p = ps[qr * AT2 + j];
            float4 v0 = *(const float4*)&vs[j * AT2 + j0];
            float4 v1 = *(const float4*)&vs[j * AT2 + j0 + 4];
            acc[0] += p * v0.x; acc[1] += p * v0.y; acc[2] += p * v0.z; acc[3] += p * v0.w;
            acc[4] += p * v1.x; acc[5] += p * v1.y; acc[6] += p * v1.z; acc[7] += p * v1.w;
        }
    }

    float invl = 1.f / l;
    size_t obase = ((size_t)(b * LQ) + half * 32 + qr) * II + h * DHD + j0;
    float o[8];
    #pragma unroll
    for (int i = 0; i < 8; i++) o[i] = acc[i] * invl;
    float th[8];
    #pragma unroll
    for (int i = 0; i < 8; i++) th[i] = __bfloat162float(__float2bfloat16_rn(o[i]));
    *(uint2*)(attHi + obase)     = make_uint2(pack2(o[0], o[1]), pack2(o[2], o[3]));
    *(uint2*)(attHi + obase + 4) = make_uint2(pack2(o[4], o[5]), pack2(o[6], o[7]));
    *(uint2*)(attLo + obase)     = make_uint2(pack2(o[0]-th[0], o[1]-th[1]), pack2(o[2]-th[2], o[3]-th[3]));
    *(uint2*)(attLo + obase + 4) = make_uint2(pack2(o[4]-th[4], o[5]-th[5]), pack2(o[6]-th[6], o[7]-th[7]));
}

// ---------------- host orchestration ----------------
#define SMEM128 ((2 * (2 * 128 * AST + 2 * GBK * BST)) * 2)
#define SMEM64  ((2 * (2 * 64  * AST + 2 * GBK * BST)) * 2)

extern "C" void kernel_launch(void* const* d_in, const int* in_sizes, int n_in,
                              void* d_out, int out_size)
{
    (void)in_sizes; (void)n_in; (void)out_size;
    const float* x        = (const float*)d_in[0];
    const int*   mask     = (const int*)  d_in[1];
    const float* latents  = (const float*)d_in[2];
    const float* ln_m_w   = (const float*)d_in[3];
    const float* ln_m_b   = (const float*)d_in[4];
    const float* ln_l_w   = (const float*)d_in[5];
    const float* ln_l_b   = (const float*)d_in[6];
    const float* Wq       = (const float*)d_in[7];
    const float* Wkv      = (const float*)d_in[8];
    const float* Wo       = (const float*)d_in[9];
    const float* ff_ln_w  = (const float*)d_in[10];
    const float* ff_ln_b  = (const float*)d_in[11];
    const float* W1       = (const float*)d_in[12];
    const float* W2       = (const float*)d_in[13];
    const float* norm_w   = (const float*)d_in[14];
    const float* norm_b   = (const float*)d_in[15];
    float* out = (float*)d_out;

    bf16 *xh, *xl, *lnlh, *lnll, *lnfh, *lnfl, *atth, *attl, *hfh, *hfl;
    bf16 *wqh, *wql, *wkvh, *wkvl, *wkvph, *wkvpl, *woh, *wol, *w1h, *w1l, *w2h, *w2l;
    float *lat, *qb, *kb, *vb, *biaskv;
    cudaGetSymbolAddress((void**)&xh, g_xh);     cudaGetSymbolAddress((void**)&xl, g_xl);
    cudaGetSymbolAddress((void**)&lnlh, g_lnlh); cudaGetSymbolAddress((void**)&lnll, g_lnll);
    cudaGetSymbolAddress((void**)&lnfh, g_lnfh); cudaGetSymbolAddress((void**)&lnfl, g_lnfl);
    cudaGetSymbolAddress((void**)&atth, g_atth); cudaGetSymbolAddress((void**)&attl, g_attl);
    cudaGetSymbolAddress((void**)&hfh, g_hfh);   cudaGetSymbolAddress((void**)&hfl, g_hfl);
    cudaGetSymbolAddress((void**)&wqh, g_wqh);   cudaGetSymbolAddress((void**)&wql, g_wql);
    cudaGetSymbolAddress((void**)&wkvh, g_wkvh); cudaGetSymbolAddress((void**)&wkvl, g_wkvl);
    cudaGetSymbolAddress((void**)&wkvph, g_wkvph); cudaGetSymbolAddress((void**)&wkvpl, g_wkvpl);
    cudaGetSymbolAddress((void**)&woh, g_woh);   cudaGetSymbolAddress((void**)&wol, g_wol);
    cudaGetSymbolAddress((void**)&w1h, g_w1h);   cudaGetSymbolAddress((void**)&w1l, g_w1l);
    cudaGetSymbolAddress((void**)&w2h, g_w2h);   cudaGetSymbolAddress((void**)&w2l, g_w2l);
    cudaGetSymbolAddress((void**)&lat, g_lat);
    cudaGetSymbolAddress((void**)&qb, g_q);
    cudaGetSymbolAddress((void**)&kb, g_k);
    cudaGetSymbolAddress((void**)&vb, g_v);
    cudaGetSymbolAddress((void**)&biaskv, g_biaskv);

    cudaFuncSetAttribute(gemm_bf16<128>, cudaFuncAttributeMaxDynamicSharedMemorySize, SMEM128);
    cudaFuncSetAttribute(gemm_bf16<64>,  cudaFuncAttributeMaxDynamicSharedMemorySize, SMEM64);
    cudaFuncSetAttribute(attn_kernel,    cudaFuncAttributeMaxDynamicSharedMemorySize, (int)ATTN_SMEM);

    // layer-invariant
    ln_split_kernel<<<BB * NN, 256>>>(x, xh, xl, nullptr, nullptr);
    init_lat_kernel<<<BB * LQ * DD / 256, 256>>>(latents, lat);

    for (int i = 0; i < NDEPTH; i++) {
        const float* Wkv_i = Wkv + (size_t)i * DD * 2 * II;
        const float* Wq_i  = Wq  + (size_t)i * DD * II;
        const float* Wo_i  = Wo  + (size_t)i * II * DD;
        const float* W1_i  = W1  + (size_t)i * DD * FFD;
        const float* W2_i  = W2  + (size_t)i * FFD * DD;

        // weight conversions
        split_kernel<<<DD * 2 * II / 1024, 256>>>(Wkv_i, ln_m_w + i * DD, wkvph, wkvpl);
        split_kernel<<<DD * 2 * II / 1024, 256>>>(Wkv_i, nullptr, wkvh, wkvl);
        split_kernel<<<DD * II / 1024, 256>>>(Wq_i, nullptr, wqh, wql);
        split_kernel<<<II * DD / 1024, 256>>>(Wo_i, nullptr, woh, wol);
        split_kernel<<<DD * FFD / 1024, 256>>>(W1_i, nullptr, w1h, w1l);
        split_kernel<<<FFD * DD / 1024, 256>>>(W2_i, nullptr, w2h, w2l);
        bias_kv_kernel<<<32, 256>>>(Wkv_i, ln_m_b + i * DD, biaskv);

        ln_split_kernel<<<BB * LQ, 256>>>(lat, lnlh, lnll, ln_l_w + i * DD, ln_l_b + i * DD);

        // q = lnl @ Wq  (fp32 out)
        gemm_bf16<64><<<dim3(II / 128, BB * LQ / 64), 256, SMEM64>>>(
            lnlh, lnll, wqh, wql, qb, BB * LQ, II, DD, EPI_NONE,
            nullptr, nullptr, nullptr, 0, 0, nullptr, nullptr);

        // kv (x part)
        gemm_bf16<128><<<dim3(2 * II / 128, BB * NN / 128), 256, SMEM128>>>(
            xh, xl, wkvph, wkvpl, nullptr, BB * NN, 2 * II, DD, EPI_KV,
            biaskv, kb, vb, NN, 0, nullptr, nullptr);

        // kv (latent part)
        gemm_bf16<64><<<dim3(2 * II / 128, BB * LQ / 64), 256, SMEM64>>>(
            lnlh, lnll, wkvh, wkvl, nullptr, BB * LQ, 2 * II, DD, EPI_KV,
            nullptr, kb, vb, LQ, NN, nullptr, nullptr);

        // attention -> split bf16
        attn_kernel<<<BB * HH * 2, 256, ATTN_SMEM>>>(qb, kb, vb, mask, atth, attl);

        // lat += att @ Wo
        gemm_bf16<64><<<dim3(DD / 128, BB * LQ / 64), 256, SMEM64>>>(
            atth, attl, woh, wol, lat, BB * LQ, DD, II, EPI_ADD,
            nullptr, nullptr, nullptr, 0, 0, nullptr, nullptr);

        // FF
        ln_split_kernel<<<BB * LQ, 256>>>(lat, lnfh, lnfl, ff_ln_w + i * DD, ff_ln_b + i * DD);
        gemm_bf16<64><<<dim3(FFD / 128, BB * LQ / 64), 256, SMEM64>>>(
            lnfh, lnfl, w1h, w1l, nullptr, BB * LQ, FFD, DD, EPI_GELU,
            nullptr, nullptr, nullptr, 0, 0, hfh, hfl);
        gemm_bf16<64><<<dim3(DD / 128, BB * LQ / 64), 256, SMEM64>>>(
            hfh, hfl, w2h, w2l, lat, BB * LQ, DD, FFD, EPI_ADD,
            nullptr, nullptr, nullptr, 0, 0, nullptr, nullptr);
    }

    ln_kernel<<<BB * LQ, 256>>>(lat, out, norm_w, norm_b);
}

// round 4
// speedup vs baseline: 2.3153x; 1.0019x over previous
#include <cuda_runtime.h>
#include <cuda_bf16.h>
#include <math.h>

// ---------------- problem constants ----------------
#define BB   16
#define NN   2048
#define DD   1024
#define HH   8
#define DHD  64
#define II   512           // H*DH
#define LQ   64
#define SSQ  2112          // N + L
#define NDEPTH 6
#define FFD  4096

typedef __nv_bfloat16 bf16;

// ---------------- scratch ----------------
__device__ bf16 g_xh[(size_t)BB * NN * DD];
__device__ bf16 g_xl[(size_t)BB * NN * DD];
__device__ bf16 g_lnlh[BB * LQ * DD],  g_lnll[BB * LQ * DD];
__device__ bf16 g_lnfh[BB * LQ * DD],  g_lnfl[BB * LQ * DD];
__device__ bf16 g_atth[BB * LQ * II],  g_attl[BB * LQ * II];
__device__ bf16 g_hfh [BB * LQ * FFD], g_hfl [BB * LQ * FFD];
__device__ bf16 g_wqh [DD * II],       g_wql [DD * II];
__device__ bf16 g_wkvh[DD * 2 * II],   g_wkvl[DD * 2 * II];
__device__ bf16 g_wkvph[DD * 2 * II],  g_wkvpl[DD * 2 * II];
__device__ bf16 g_woh [II * DD],       g_wol [II * DD];
__device__ bf16 g_w1h [DD * FFD],      g_w1l [DD * FFD];
__device__ bf16 g_w2h [FFD * DD],      g_w2l [FFD * DD];
__device__ float g_lat[BB * LQ * DD];
__device__ float g_q  [BB * LQ * II];
__device__ float g_k  [(size_t)BB * HH * SSQ * DHD];
__device__ float g_v  [(size_t)BB * HH * SSQ * DHD];
__device__ float g_biaskv[2 * II];

// ---------------- helpers ----------------
__device__ __forceinline__ unsigned pack2(float x, float y)
{
    bf16 hx = __float2bfloat16_rn(x);
    bf16 hy = __float2bfloat16_rn(y);
    return (unsigned)__bfloat16_as_ushort(hx) | ((unsigned)__bfloat16_as_ushort(hy) << 16);
}
__device__ __forceinline__ void split4(float4 v, uint2& hi, uint2& lo)
{
    float hx = __bfloat162float(__float2bfloat16_rn(v.x));
    float hy = __bfloat162float(__float2bfloat16_rn(v.y));
    float hz = __bfloat162float(__float2bfloat16_rn(v.z));
    float hw = __bfloat162float(__float2bfloat16_rn(v.w));
    hi = make_uint2(pack2(v.x, v.y), pack2(v.z, v.w));
    lo = make_uint2(pack2(v.x - hx, v.y - hy), pack2(v.z - hz, v.w - hw));
}

// ---------------- LayerNorm (fp32 out, final layer) ----------------
__global__ __launch_bounds__(256) void ln_kernel(const float* __restrict__ in,
                                                 float* __restrict__ out,
                                                 const float* __restrict__ w,
                                                 const float* __restrict__ b)
{
    int row = blockIdx.x;
    int tid = threadIdx.x;
    const float4 xv = *(const float4*)(in + (size_t)row * DD + tid * 4);
    float s  = xv.x + xv.y + xv.z + xv.w;
    float ss = xv.x * xv.x + xv.y * xv.y + xv.z * xv.z + xv.w * xv.w;
    #pragma unroll
    for (int o = 16; o; o >>= 1) {
        s  += __shfl_xor_sync(0xffffffffu, s,  o);
        ss += __shfl_xor_sync(0xffffffffu, ss, o);
    }
    __shared__ float red[16];
    int wid = tid >> 5;
    if ((tid & 31) == 0) { red[wid] = s; red[wid + 8] = ss; }
    __syncthreads();
    s = 0.f; ss = 0.f;
    #pragma unroll
    for (int i = 0; i < 8; i++) { s += red[i]; ss += red[i + 8]; }
    float mu   = s * (1.f / DD);
    float var  = ss * (1.f / DD) - mu * mu;
    float rstd = rsqrtf(var + 1e-5f);
    float4 o4;
    o4.x = (xv.x - mu) * rstd; o4.y = (xv.y - mu) * rstd;
    o4.z = (xv.z - mu) * rstd; o4.w = (xv.w - mu) * rstd;
    const float4 wv = *(const float4*)(w + tid * 4);
    const float4 bv = *(const float4*)(b + tid * 4);
    o4.x = o4.x * wv.x + bv.x; o4.y = o4.y * wv.y + bv.y;
    o4.z = o4.z * wv.z + bv.z; o4.w = o4.w * wv.w + bv.w;
    *(float4*)(out + (size_t)row * DD + tid * 4) = o4;
}

// ---------------- LayerNorm -> split bf16 hi/lo ----------------
__global__ __launch_bounds__(256) void ln_split_kernel(const float* __restrict__ in,
                                                       bf16* __restrict__ hi,
                                                       bf16* __restrict__ lo,
                                                       const float* __restrict__ w,
                                                       const float* __restrict__ b)
{
    int row = blockIdx.x;
    int tid = threadIdx.x;
    const float4 xv = *(const float4*)(in + (size_t)row * DD + tid * 4);
    float s  = xv.x + xv.y + xv.z + xv.w;
    float ss = xv.x * xv.x + xv.y * xv.y + xv.z * xv.z + xv.w * xv.w;
    #pragma unroll
    for (int o = 16; o; o >>= 1) {
        s  += __shfl_xor_sync(0xffffffffu, s,  o);
        ss += __shfl_xor_sync(0xffffffffu, ss, o);
    }
    __shared__ float red[16];
    int wid = tid >> 5;
    if ((tid & 31) == 0) { red[wid] = s; red[wid + 8] = ss; }
    __syncthreads();
    s = 0.f; ss = 0.f;
    #pragma unroll
    for (int i = 0; i < 8; i++) { s += red[i]; ss += red[i + 8]; }
    float mu   = s * (1.f / DD);
    float var  = ss * (1.f / DD) - mu * mu;
    float rstd = rsqrtf(var + 1e-5f);
    float4 o4;
    o4.x = (xv.x - mu) * rstd; o4.y = (xv.y - mu) * rstd;
    o4.z = (xv.z - mu) * rstd; o4.w = (xv.w - mu) * rstd;
    if (w) {
        const float4 wv = *(const float4*)(w + tid * 4);
        const float4 bv = *(const float4*)(b + tid * 4);
        o4.x = o4.x * wv.x + bv.x; o4.y = o4.y * wv.y + bv.y;
        o4.z = o4.z * wv.z + bv.z; o4.w = o4.w * wv.w + bv.w;
    }
    uint2 h, l;
    split4(o4, h, l);
    *(uint2*)(hi + (size_t)row * DD + tid * 4) = h;
    *(uint2*)(lo + (size_t)row * DD + tid * 4) = l;
}

// ---------------- generic split (weights), optional per-row(1024) scale ------
__global__ __launch_bounds__(256) void split_kernel(const float* __restrict__ in,
                                                    const float* __restrict__ rowscale,
                                                    bf16* __restrict__ hi,
                                                    bf16* __restrict__ lo)
{
    int idx = (blockIdx.x * 256 + threadIdx.x) * 4;
    float4 v = *(const float4*)(in + idx);
    if (rowscale) {
        float sc = rowscale[idx >> 10];
        v.x *= sc; v.y *= sc; v.z *= sc; v.w *= sc;
    }
    uint2 h, l;
    split4(v, h, l);
    *(uint2*)(hi + idx) = h;
    *(uint2*)(lo + idx) = l;
}

// ---------------- lat init ----------------
__global__ void init_lat_kernel(const float* __restrict__ latents, float* __restrict__ lat)
{
    int idx = blockIdx.x * 256 + threadIdx.x;
    lat[idx] = latents[idx & (LQ * DD - 1)];
}

// ---------------- biaskv[j] = sum_d ln_m_b[d] * Wkv[d][j] ----------------
__global__ void bias_kv_kernel(const float* __restrict__ Wkv, const float* __restrict__ lnb,
                               float* __restrict__ bias)
{
    int j  = blockIdx.x * 32 + (threadIdx.x & 31);
    int dc = threadIdx.x >> 5;
    float a = 0.f;
    int d0 = dc * 128;
    #pragma unroll 8
    for (int d = d0; d < d0 + 128; d++) a += lnb[d] * Wkv[(size_t)d * 1024 + j];
    __shared__ float red[8][32];
    red[dc][threadIdx.x & 31] = a;
    __syncthreads();
    if (dc == 0) {
        float s = 0.f;
        #pragma unroll
        for (int i = 0; i < 8; i++) s += red[i][threadIdx.x & 31];
        bias[j] = s;
    }
}

// ================= bf16x3 split-precision tensor-core GEMM =================
enum { EPI_NONE = 0, EPI_ADD = 1, EPI_GELU = 2, EPI_KV = 3 };

#define GBK 32
#define AST 40
#define BST 136

__device__ __forceinline__ void mma16816(float* d, const unsigned* a, const unsigned* b)
{
    asm volatile(
        "mma.sync.aligned.m16n8k16.row.col.f32.bf16.bf16.f32 "
        "{%0,%1,%2,%3}, {%4,%5,%6,%7}, {%8,%9}, {%0,%1,%2,%3};\n"
        : "+f"(d[0]), "+f"(d[1]), "+f"(d[2]), "+f"(d[3])
        : "r"(a[0]), "r"(a[1]), "r"(a[2]), "r"(a[3]), "r"(b[0]), "r"(b[1]));
}
__device__ __forceinline__ void ldsm4(unsigned* r, unsigned addr)
{
    asm volatile("ldmatrix.sync.aligned.m8n8.x4.shared.b16 {%0,%1,%2,%3}, [%4];\n"
                 : "=r"(r[0]), "=r"(r[1]), "=r"(r[2]), "=r"(r[3]) : "r"(addr));
}
__device__ __forceinline__ void ldsm4t(unsigned* r, unsigned addr)
{
    asm volatile("ldmatrix.sync.aligned.m8n8.x4.trans.shared.b16 {%0,%1,%2,%3}, [%4];\n"
                 : "=r"(r[0]), "=r"(r[1]), "=r"(r[2]), "=r"(r[3]) : "r"(addr));
}
__device__ __forceinline__ void cpasync16(unsigned s, const void* g)
{
    asm volatile("cp.async.cg.shared.global [%0], [%1], 16;\n" :: "r"(s), "l"(g));
}
#define CP_COMMIT() asm volatile("cp.async.commit_group;\n")
#define CP_WAIT1()  asm volatile("cp.async.wait_group 1;\n")

template<int TM>
__global__ __launch_bounds__(256) void gemm_bf16(
    const bf16* __restrict__ Ahi, const bf16* __restrict__ Alo,
    const bf16* __restrict__ Bhi, const bf16* __restrict__ Blo,
    float* __restrict__ C, int M, int N, int K, int epi,
    const float* __restrict__ bias,
    float* __restrict__ Kout, float* __restrict__ Vout, int rowsPerB, int sBase,
    bf16* __restrict__ OutHi, bf16* __restrict__ OutLo)
{
    constexpr int WM16   = TM / 32;
    constexpr int A_EL   = TM * AST;
    constexpr int B_EL   = GBK * BST;
    constexpr int STAGE  = 2 * A_EL + 2 * B_EL;      // elements per stage
    extern __shared__ __align__(16) bf16 smg[];
    unsigned base = (unsigned)__cvta_generic_to_shared(smg);

    int tid  = threadIdx.x;
    int lane = tid & 31;
    int warp = tid >> 5;
    int wm = warp & 1, wn = warp >> 1;
    int row0 = blockIdx.y * TM;
    int col0 = blockIdx.x << 7;
    int lr = (lane & 7) + (((lane >> 3) & 1) << 3);
    int lc = (lane >> 4) << 3;

    float acc[WM16][4][4];
    #pragma unroll
    for (int i = 0; i < WM16; i++)
        #pragma unroll
        for (int j = 0; j < 4; j++)
            #pragma unroll
            for (int t = 0; t < 4; t++) acc[i][j][t] = 0.f;

    auto load_stage = [&](int kt, int buf) {
        unsigned sb = base + (unsigned)buf * STAGE * 2;
        constexpr int ACH = (TM * 4) / 256;
        #pragma unroll
        for (int p = 0; p < 2; p++) {
            const bf16* Ap = p ? Alo : Ahi;
            unsigned so = sb + (unsigned)p * A_EL * 2;
            #pragma unroll
            for (int i = 0; i < ACH; i++) {
                int chunk = tid + i * 256;
                int r = chunk >> 2, c16 = chunk & 3;
                cpasync16(so + (unsigned)(r * AST + c16 * 8) * 2,
                          Ap + (size_t)(row0 + r) * K + kt + c16 * 8);
            }
        }
        #pragma unroll
        for (int p = 0; p < 2; p++) {
            const bf16* Bp = p ? Blo : Bhi;
            unsigned so = sb + (unsigned)(2 * A_EL + p * B_EL) * 2;
            #pragma unroll
            for (int i = 0; i < 2; i++) {
                int chunk = tid + i * 256;
                int r = chunk >> 4, cc = (chunk & 15) * 8;
                cpasync16(so + (unsigned)(r * BST + cc) * 2,
                          Bp + (size_t)(kt + r) * N + col0 + cc);
            }
        }
    };

    int NK = K / GBK;
    load_stage(0, 0);   CP_COMMIT();
    load_stage(GBK, 1); CP_COMMIT();

    for (int it = 0; it < NK; it++) {
        CP_WAIT1();
        __syncthreads();
        unsigned sb  = base + (unsigned)(it & 1) * STAGE * 2;
        unsigned aHi = sb;
        unsigned aLo = sb + A_EL * 2;
        unsigned bHi = sb + 2 * A_EL * 2;
        unsigned bLo = bHi + B_EL * 2;

        #pragma unroll
        for (int k16 = 0; k16 < GBK; k16 += 16) {
            unsigned ah[WM16][4], al[WM16][4], bh[2][4], bl[2][4];
            #pragma unroll
            for (int mi = 0; mi < WM16; mi++) {
                unsigned off = (unsigned)((wm * (TM / 2) + mi * 16 + lr) * AST + k16 + lc) * 2;
                ldsm4(ah[mi], aHi + off);
                ldsm4(al[mi], aLo + off);
            }
            #pragma unroll
            for (int ni = 0; ni < 2; ni++) {
                unsigned off = (unsigned)((k16 + lr) * BST + wn * 32 + ni * 16 + lc) * 2;
                ldsm4t(bh[ni], bHi + off);
                ldsm4t(bl[ni], bLo + off);
            }
            #pragma unroll
            for (int mi = 0; mi < WM16; mi++) {
                #pragma unroll
                for (int nj = 0; nj < 4; nj++) {
                    int ni = nj >> 1, p = nj & 1;
                    mma16816(acc[mi][nj], ah[mi], &bh[ni][2 * p]);
                    mma16816(acc[mi][nj], ah[mi], &bl[ni][2 * p]);
                    mma16816(acc[mi][nj], al[mi], &bh[ni][2 * p]);
                }
            }
        }
        __syncthreads();
        if (it + 2 < NK) load_stage((it + 2) * GBK, it & 1);
        CP_COMMIT();
    }

    // ---------------- epilogue ----------------
    int rbase = row0 + wm * (TM / 2) + (lane >> 2);
    int cbase = col0 + wn * 32 + (lane & 3) * 2;
    #pragma unroll
    for (int mi = 0; mi < WM16; mi++) {
        #pragma unroll
        for (int nj = 0; nj < 4; nj++) {
            #pragma unroll
            for (int half = 0; half < 2; half++) {
                int r = rbase + mi * 16 + half * 8;
                int c = cbase + nj * 8;
                float v0 = acc[mi][nj][half * 2 + 0];
                float v1 = acc[mi][nj][half * 2 + 1];
                if (epi == EPI_KV) {
                    if (bias) { v0 += bias[c]; v1 += bias[c + 1]; }
                    int bb = r / rowsPerB;
                    int s  = sBase + (r - bb * rowsPerB);
                    float* dst;
                    if (c < II)
                        dst = Kout + (((size_t)bb * HH + (c >> 6)) * SSQ + s) * DHD + (c & 63);
                    else
                        dst = Vout + (((size_t)bb * HH + ((c - II) >> 6)) * SSQ + s) * DHD + ((c - II) & 63);
                    dst[0] = v0; dst[1] = v1;
                } else if (epi == EPI_GELU) {
                    float h0 = 0.5f * v0 * (1.f + erff(v0 * 0.70710678118654752f));
                    float h1 = 0.5f * v1 * (1.f + erff(v1 * 0.70710678118654752f));
                    float t0 = __bfloat162float(__float2bfloat16_rn(h0));
                    float t1 = __bfloat162float(__float2bfloat16_rn(h1));
                    *(unsigned*)(OutHi + (size_t)r * N + c) = pack2(h0, h1);
                    *(unsigned*)(OutLo + (size_t)r * N + c) = pack2(h0 - t0, h1 - t1);
                } else {
                    float* dst = C + (size_t)r * N + c;
                    if (epi == EPI_ADD) { v0 += dst[0]; v1 += dst[1]; }
                    dst[0] = v0; dst[1] = v1;
                }
            }
        }
    }
}

// ---------------- fused flash attention v2 ----------------
// 2 CTAs per (b,h): each handles 32 q rows, all S. K stored d-major in smem.
#define AT2  68
#define ATTN_SMEM (((size_t)(32 + 64 + 64 + 32) * AT2 + 64) * 4)

__global__ __launch_bounds__(256) void attn_kernel(
    const float* __restrict__ q, const float* __restrict__ kg, const float* __restrict__ vg,
    const int* __restrict__ mask, bf16* __restrict__ attHi, bf16* __restrict__ attLo)
{
    extern __shared__ float sm[];
    float* qs  = sm;                              // [32][AT2] : q rows, d cols
    float* kT  = sm + 32 * AT2;                   // [64][AT2] : kT[d][s]
    float* vs  = sm + (32 + 64) * AT2;            // [64][AT2] : v rows s, d cols
    float* ps  = sm + (32 + 128) * AT2;           // [32][AT2]
    float* msk = sm + (32 + 160) * AT2;           // [64]

    int blk = blockIdx.x;
    int bh = blk >> 1, half = blk & 1;
    int b = bh >> 3, h = bh & 7;
    int tid = threadIdx.x;
    int qr = tid >> 3;                 // 0..31
    int j0 = (tid & 7) * 8;            // this thread's 8 score cols / 8 dh cols

    const float* qbase = q + ((size_t)(b * LQ) + half * 32) * II + h * DHD;
    for (int idx = tid; idx < 32 * 16; idx += 256) {
        int r = idx >> 4, d4 = (idx & 15) << 2;
        *(float4*)&qs[r * AT2 + d4] = *(const float4*)&qbase[(size_t)r * II + d4];
    }

    float acc[8];
    #pragma unroll
    for (int i = 0; i < 8; i++) acc[i] = 0.f;
    float m = -1e30f, l = 0.f;

    const float* kb = kg + ((size_t)b * HH + h) * SSQ * DHD;
    const float* vb = vg + ((size_t)b * HH + h) * SSQ * DHD;
    const int* mrow = mask + b * NN;

    for (int t = 0; t < SSQ / 64; t++) {
        int s0 = t * 64;
        __syncthreads();
        for (int idx = tid; idx < 64 * 16; idx += 256) {
            int r = idx >> 4, d4 = (idx & 15) << 2;
            float4 k4 = *(const float4*)&kb[(size_t)(s0 + r) * DHD + d4];
            kT[(d4 + 0) * AT2 + r] = k4.x;
            kT[(d4 + 1) * AT2 + r] = k4.y;
            kT[(d4 + 2) * AT2 + r] = k4.z;
            kT[(d4 + 3) * AT2 + r] = k4.w;
            *(float4*)&vs[r * AT2 + d4] = *(const float4*)&vb[(size_t)(s0 + r) * DHD + d4];
        }
        if (tid < 64) {
            int s = s0 + tid;
            msk[tid] = (s < NN && mrow[s] == 1) ? 1.f : 0.f;
        }
        __syncthreads();

        float sc[8];
        #pragma unroll
        for (int j = 0; j < 8; j++) sc[j] = 0.f;
        const float* qrow = &qs[qr * AT2];
        #pragma unroll 8
        for (int d = 0; d < 64; d++) {
            float qv = qrow[d];
            float4 kA = *(const float4*)&kT[d * AT2 + j0];
            float4 kB = *(const float4*)&kT[d * AT2 + j0 + 4];
            sc[0] += qv * kA.x; sc[1] += qv * kA.y; sc[2] += qv * kA.z; sc[3] += qv * kA.w;
            sc[4] += qv * kB.x; sc[5] += qv * kB.y; sc[6] += qv * kB.z; sc[7] += qv * kB.w;
        }
        float tmax = -1e30f;
        #pragma unroll
        for (int j = 0; j < 8; j++) {
            float s = sc[j] * 0.125f;
            if (msk[j0 + j] != 0.f) s = -1e30f;
            sc[j] = s;
            tmax = fmaxf(tmax, s);
        }
        tmax = fmaxf(tmax, __shfl_xor_sync(0xffffffffu, tmax, 1));
        tmax = fmaxf(tmax, __shfl_xor_sync(0xffffffffu, tmax, 2));
        tmax = fmaxf(tmax, __shfl_xor_sync(0xffffffffu, tmax, 4));
        float mnew = fmaxf(m, tmax);
        float corr = __expf(m - mnew);
        float psum = 0.f;
        #pragma unroll
        for (int j = 0; j < 8; j++) {
            float p = __expf(sc[j] - mnew);
            ps[qr * AT2 + j0 + j] = p;
            psum += p;
        }
        psum += __shfl_xor_sync(0xffffffffu, psum, 1);
        psum += __shfl_xor_sync(0xffffffffu, psum, 2);
        psum += __shfl_xor_sync(0xffffffffu, psum, 4);
        l = l * corr + psum;
        m = mnew;
        #pragma unroll
        for (int i = 0; i < 8; i++) acc[i] *= corr;
        __syncwarp();

        #pragma unroll 4
        for (int j = 0; j < 64; j++) {
            float p = ps[qr * AT2 + j];
            float4 v0 = *(const float4*)&vs[j * AT2 + j0];
            float4 v1 = *(const float4*)&vs[j * AT2 + j0 + 4];
            acc[0] += p * v0.x; acc[1] += p * v0.y; acc[2] += p * v0.z; acc[3] += p * v0.w;
            acc[4] += p * v1.x; acc[5] += p * v1.y; acc[6] += p * v1.z; acc[7] += p * v1.w;
        }
    }

    float invl = 1.f / l;
    size_t obase = ((size_t)(b * LQ) + half * 32 + qr) * II + h * DHD + j0;
    float o[8];
    #pragma unroll
    for (int i = 0; i < 8; i++) o[i] = acc[i] * invl;
    float th[8];
    #pragma unroll
    for (int i = 0; i < 8; i++) th[i] = __bfloat162float(__float2bfloat16_rn(o[i]));
    *(uint2*)(attHi + obase)     = make_uint2(pack2(o[0], o[1]), pack2(o[2], o[3]));
    *(uint2*)(attHi + obase + 4) = make_uint2(pack2(o[4], o[5]), pack2(o[6], o[7]));
    *(uint2*)(attLo + obase)     = make_uint2(pack2(o[0]-th[0], o[1]-th[1]), pack2(o[2]-th[2], o[3]-th[3]));
    *(uint2*)(attLo + obase + 4) = make_uint2(pack2(o[4]-th[4], o[5]-th[5]), pack2(o[6]-th[6], o[7]-th[7]));
}

// ---------------- host orchestration ----------------
#define SMEM128 ((2 * (2 * 128 * AST + 2 * GBK * BST)) * 2)
#define SMEM64  ((2 * (2 * 64  * AST + 2 * GBK * BST)) * 2)

extern "C" void kernel_launch(void* const* d_in, const int* in_sizes, int n_in,
                              void* d_out, int out_size)
{
    (void)in_sizes; (void)n_in; (void)out_size;
    const float* x        = (const float*)d_in[0];
    const int*   mask     = (const int*)  d_in[1];
    const float* latents  = (const float*)d_in[2];
    const float* ln_m_w   = (const float*)d_in[3];
    const float* ln_m_b   = (const float*)d_in[4];
    const float* ln_l_w   = (const float*)d_in[5];
    const float* ln_l_b   = (const float*)d_in[6];
    const float* Wq       = (const float*)d_in[7];
    const float* Wkv      = (const float*)d_in[8];
    const float* Wo       = (const float*)d_in[9];
    const float* ff_ln_w  = (const float*)d_in[10];
    const float* ff_ln_b  = (const float*)d_in[11];
    const float* W1       = (const float*)d_in[12];
    const float* W2       = (const float*)d_in[13];
    const float* norm_w   = (const float*)d_in[14];
    const float* norm_b   = (const float*)d_in[15];
    float* out = (float*)d_out;

    bf16 *xh, *xl, *lnlh, *lnll, *lnfh, *lnfl, *atth, *attl, *hfh, *hfl;
    bf16 *wqh, *wql, *wkvh, *wkvl, *wkvph, *wkvpl, *woh, *wol, *w1h, *w1l, *w2h, *w2l;
    float *lat, *qb, *kb, *vb, *biaskv;
    cudaGetSymbolAddress((void**)&xh, g_xh);     cudaGetSymbolAddress((void**)&xl, g_xl);
    cudaGetSymbolAddress((void**)&lnlh, g_lnlh); cudaGetSymbolAddress((void**)&lnll, g_lnll);
    cudaGetSymbolAddress((void**)&lnfh, g_lnfh); cudaGetSymbolAddress((void**)&lnfl, g_lnfl);
    cudaGetSymbolAddress((void**)&atth, g_atth); cudaGetSymbolAddress((void**)&attl, g_attl);
    cudaGetSymbolAddress((void**)&hfh, g_hfh);   cudaGetSymbolAddress((void**)&hfl, g_hfl);
    cudaGetSymbolAddress((void**)&wqh, g_wqh);   cudaGetSymbolAddress((void**)&wql, g_wql);
    cudaGetSymbolAddress((void**)&wkvh, g_wkvh); cudaGetSymbolAddress((void**)&wkvl, g_wkvl);
    cudaGetSymbolAddress((void**)&wkvph, g_wkvph); cudaGetSymbolAddress((void**)&wkvpl, g_wkvpl);
    cudaGetSymbolAddress((void**)&woh, g_woh);   cudaGetSymbolAddress((void**)&wol, g_wol);
    cudaGetSymbolAddress((void**)&w1h, g_w1h);   cudaGetSymbolAddress((void**)&w1l, g_w1l);
    cudaGetSymbolAddress((void**)&w2h, g_w2h);   cudaGetSymbolAddress((void**)&w2l, g_w2l);
    cudaGetSymbolAddress((void**)&lat, g_lat);
    cudaGetSymbolAddress((void**)&qb, g_q);
    cudaGetSymbolAddress((void**)&kb, g_k);
    cudaGetSymbolAddress((void**)&vb, g_v);
    cudaGetSymbolAddress((void**)&biaskv, g_biaskv);

    cudaFuncSetAttribute(gemm_bf16<128>, cudaFuncAttributeMaxDynamicSharedMemorySize, SMEM128);
    cudaFuncSetAttribute(gemm_bf16<64>,  cudaFuncAttributeMaxDynamicSharedMemorySize, SMEM64);
    cudaFuncSetAttribute(attn_kernel,    cudaFuncAttributeMaxDynamicSharedMemorySize, (int)ATTN_SMEM);

    // layer-invariant
    ln_split_kernel<<<BB * NN, 256>>>(x, xh, xl, nullptr, nullptr);
    init_lat_kernel<<<BB * LQ * DD / 256, 256>>>(latents, lat);

    for (int i = 0; i < NDEPTH; i++) {
        const float* Wkv_i = Wkv + (size_t)i * DD * 2 * II;
        const float* Wq_i  = Wq  + (size_t)i * DD * II;
        const float* Wo_i  = Wo  + (size_t)i * II * DD;
        const float* W1_i  = W1  + (size_t)i * DD * FFD;
        const float* W2_i  = W2  + (size_t)i * FFD * DD;

        // weight conversions
        split_kernel<<<DD * 2 * II / 1024, 256>>>(Wkv_i, ln_m_w + i * DD, wkvph, wkvpl);
        split_kernel<<<DD * 2 * II / 1024, 256>>>(Wkv_i, nullptr, wkvh, wkvl);
        split_kernel<<<DD * II / 1024, 256>>>(Wq_i, nullptr, wqh, wql);
        split_kernel<<<II * DD / 1024, 256>>>(Wo_i, nullptr, woh, wol);
        split_kernel<<<DD * FFD / 1024, 256>>>(W1_i, nullptr, w1h, w1l);
        split_kernel<<<FFD * DD / 1024, 256>>>(W2_i, nullptr, w2h, w2l);
        bias_kv_kernel<<<32, 256>>>(Wkv_i, ln_m_b + i * DD, biaskv);

        ln_split_kernel<<<BB * LQ, 256>>>(lat, lnlh, lnll, ln_l_w + i * DD, ln_l_b + i * DD);

        // q = lnl @ Wq  (fp32 out)
        gemm_bf16<64><<<dim3(II / 128, BB * LQ / 64), 256, SMEM64>>>(
            lnlh, lnll, wqh, wql, qb, BB * LQ, II, DD, EPI_NONE,
            nullptr, nullptr, nullptr, 0, 0, nullptr, nullptr);

        // kv (x part)
        gemm_bf16<128><<<dim3(2 * II / 128, BB * NN / 128), 256, SMEM128>>>(
            xh, xl, wkvph, wkvpl, nullptr, BB * NN, 2 * II, DD, EPI_KV,
            biaskv, kb, vb, NN, 0, nullptr, nullptr);

        // kv (latent part)
        gemm_bf16<64><<<dim3(2 * II / 128, BB * LQ / 64), 256, SMEM64>>>(
            lnlh, lnll, wkvh, wkvl, nullptr, BB * LQ, 2 * II, DD, EPI_KV,
            nullptr, kb, vb, LQ, NN, nullptr, nullptr);

        // attention -> split bf16
        attn_kernel<<<BB * HH * 2, 256, ATTN_SMEM>>>(qb, kb, vb, mask, atth, attl);

        // lat += att @ Wo
        gemm_bf16<64><<<dim3(DD / 128, BB * LQ / 64), 256, SMEM64>>>(
            atth, attl, woh, wol, lat, BB * LQ, DD, II, EPI_ADD,
            nullptr, nullptr, nullptr, 0, 0, nullptr, nullptr);

        // FF
        ln_split_kernel<<<BB * LQ, 256>>>(lat, lnfh, lnfl, ff_ln_w + i * DD, ff_ln_b + i * DD);
        gemm_bf16<64><<<dim3(FFD / 128, BB * LQ / 64), 256, SMEM64>>>(
            lnfh, lnfl, w1h, w1l, nullptr, BB * LQ, FFD, DD, EPI_GELU,
            nullptr, nullptr, nullptr, 0, 0, hfh, hfl);
        gemm_bf16<64><<<dim3(DD / 128, BB * LQ / 64), 256, SMEM64>>>(
            hfh, hfl, w2h, w2l, lat, BB * LQ, DD, FFD, EPI_ADD,
            nullptr, nullptr, nullptr, 0, 0, nullptr, nullptr);
    }

    ln_kernel<<<BB * LQ, 256>>>(lat, out, norm_w, norm_b);
}